// round 9
// baseline (speedup 1.0000x reference)
#include <cuda_runtime.h>
#include <cstdint>
#include <math.h>

#define S_LEN  2048
#define G_GRP  2
#define EMB    1024
#define NH     16
#define NKV    4
#define HD     64
#define MROWS  (S_LEN * G_GRP)      // 4096
#define KVW    (NKV * HD)           // 256
#define ROWQ   (G_GRP * EMB)        // 2048
#define ROWK   (G_GRP * KVW)        // 512

// ---------------- scratch ----------------
__device__ float g_X[MROWS * EMB];
__device__ float g_Q[MROWS * EMB];
__device__ float g_K[MROWS * KVW];
__device__ float g_V[MROWS * KVW];                 // natural [m][kvh*64+d]
__device__ float g_VT[G_GRP * NKV * HD * S_LEN];   // [(grp*4+kvh)*64 + d][seq]
__device__ float g_O[MROWS * EMB];
__device__ float g_WT[(EMB + 2 * KVW) * EMB];
__device__ float g_WoT[EMB * EMB];

// ================= helpers =================
__device__ __forceinline__ uint32_t smem_u32(const void* p) {
    uint32_t a;
    asm("{ .reg .u64 t; cvta.to.shared.u64 t, %1; cvt.u32.u64 %0, t; }" : "=r"(a) : "l"(p));
    return a;
}
__device__ __forceinline__ uint32_t f2tf32(float x) {
    uint32_t r;
    asm("cvt.rna.tf32.f32 %0, %1;" : "=r"(r) : "f"(x));
    return r;
}
__device__ __forceinline__ float rtf(float x) { return __uint_as_float(f2tf32(x)); }

__device__ __forceinline__ void mma_tf32(float c[4], const uint32_t a[4], const uint32_t b[2]) {
    asm volatile(
        "mma.sync.aligned.m16n8k8.row.col.f32.tf32.tf32.f32 "
        "{%0,%1,%2,%3}, {%4,%5,%6,%7}, {%8,%9}, {%0,%1,%2,%3};"
        : "+f"(c[0]), "+f"(c[1]), "+f"(c[2]), "+f"(c[3])
        : "r"(a[0]), "r"(a[1]), "r"(a[2]), "r"(a[3]), "r"(b[0]), "r"(b[1]));
}

__device__ __forceinline__ void ldsm_x4(uint32_t r[4], uint32_t addr) {
    asm volatile("ldmatrix.sync.aligned.m8n8.x4.shared.b16 {%0,%1,%2,%3}, [%4];"
        : "=r"(r[0]), "=r"(r[1]), "=r"(r[2]), "=r"(r[3]) : "r"(addr));
}
__device__ __forceinline__ int ldsmA_off(int lane, int stride) {
    return ((lane & 7) + ((lane >> 3) & 1) * 8) * stride + (lane >> 4) * 4;
}
__device__ __forceinline__ int ldsmB_off(int lane, int stride) {
    return ((lane & 7) + ((lane >> 4) & 1) * 8) * stride + ((lane >> 3) & 1) * 4;
}

__device__ __forceinline__ void cpa16(uint32_t dst, const float* src) {
    asm volatile("cp.async.cg.shared.global [%0], [%1], 16;" :: "r"(dst), "l"(src));
}
__device__ __forceinline__ void cpa_commit() { asm volatile("cp.async.commit_group;"); }
template <int N>
__device__ __forceinline__ void cpa_wait() { asm volatile("cp.async.wait_group %0;" :: "n"(N)); }

// ================= producer-side prep =================
__global__ __launch_bounds__(1024) void transpose_all(
    const float* __restrict__ Wq, const float* __restrict__ Wk,
    const float* __restrict__ Wv, const float* __restrict__ Wo)
{
    __shared__ float t[32][33];
    const int bx = blockIdx.x;
    const float* W; float* WT; int N; int nb;
    if (bx < 32)      { W = Wq; WT = g_WT;                               N = EMB; nb = bx; }
    else if (bx < 40) { W = Wk; WT = g_WT + (size_t)EMB * EMB;           N = KVW; nb = bx - 32; }
    else if (bx < 48) { W = Wv; WT = g_WT + (size_t)(EMB + KVW) * EMB;   N = KVW; nb = bx - 40; }
    else              { W = Wo; WT = g_WoT;                              N = EMB; nb = bx - 48; }

    int n = nb * 32 + threadIdx.x;
    int k = blockIdx.y * 32 + threadIdx.y;
    t[threadIdx.y][threadIdx.x] = rtf(W[(size_t)k * N + n]);
    __syncthreads();
    int n2 = nb * 32 + threadIdx.y;
    int k2 = blockIdx.y * 32 + threadIdx.x;
    WT[(size_t)n2 * EMB + k2] = t[threadIdx.x][threadIdx.y];
}

__global__ __launch_bounds__(512) void round_x(const float* __restrict__ x) {
    int i = blockIdx.x * 512 + threadIdx.x;
    float4 v = reinterpret_cast<const float4*>(x)[i];
    reinterpret_cast<float4*>(g_X)[i] = make_float4(rtf(v.x), rtf(v.y), rtf(v.z), rtf(v.w));
}

// coalesced V transpose: g_V[m][c] -> g_VT[(m&1)*256 + c][m>>1]
__global__ __launch_bounds__(256) void transpose_v() {
    __shared__ float t[64][33];
    const int mt = blockIdx.x;
    const int ct = blockIdx.y;
    const int tx = threadIdx.x & 31;
    const int ty = threadIdx.x >> 5;
#pragma unroll
    for (int k = 0; k < 8; k++) {
        int ml = ty + k * 8;
        t[ml][tx] = g_V[(size_t)(mt * 64 + ml) * KVW + ct * 32 + tx];
    }
    __syncthreads();
#pragma unroll
    for (int k = 0; k < 8; k++) {
        int rs  = ty + k * 8;
        int grp = rs >> 5, c = rs & 31;
        g_VT[(size_t)(grp * 256 + ct * 32 + c) * S_LEN + mt * 32 + tx] = t[grp + 2 * tx][c];
    }
}

// ================= tf32 mma GEMM: 2-stage, single sync per chunk =============
#define AST 36
#define ABUF (128 * AST)
#define GEMM_SMEM (4 * ABUF * 4)     // 73728 B

template <bool ROUND>
__device__ __forceinline__ void gemm_tile(
    const float* __restrict__ A, const float* __restrict__ BT,
    float* __restrict__ C, int ldc, int m0, int n0bt, int c0)
{
    extern __shared__ uint32_t dsm[];
    const uint32_t sb = smem_u32(dsm);

    const int tid  = threadIdx.x;      // 0..127
    const int lane = tid & 31;
    const int wid  = tid >> 5;
    const int wm   = wid >> 1;
    const int wn   = wid & 1;
    const int g    = lane >> 2;
    const int tg   = lane & 3;

    float acc[4][8][4];
#pragma unroll
    for (int mi = 0; mi < 4; mi++)
#pragma unroll
        for (int nt = 0; nt < 8; nt++)
#pragma unroll
            for (int j = 0; j < 4; j++) acc[mi][nt][j] = 0.0f;

    const int row = tid >> 3;
    const int q   = (tid & 7) * 4;

    auto stage = [&](int c, int buf) {
        const int k0 = c * 32;
        const uint32_t aBase = sb + (uint32_t)(2 * buf) * ABUF * 4;
        const uint32_t bBase = aBase + ABUF * 4;
#pragma unroll
        for (int t = 0; t < 8; t++) {
            int r = row + t * 16;
            cpa16(aBase + (uint32_t)(r * AST + q) * 4, &A [(size_t)(m0 + r) * EMB + k0 + q]);
            cpa16(bBase + (uint32_t)(r * AST + q) * 4, &BT[(size_t)(n0bt + r) * EMB + k0 + q]);
        }
    };

    uint32_t aOff[4], bOff[4];
    {
        const int la = ldsmA_off(lane, AST);
        const int lb = ldsmB_off(lane, AST);
#pragma unroll
        for (int mi = 0; mi < 4; mi++)
            aOff[mi] = (uint32_t)(((wm * 64 + mi * 16) * AST + la) * 4);
#pragma unroll
        for (int pr = 0; pr < 4; pr++)
            bOff[pr] = (uint32_t)(((wn * 64 + pr * 16) * AST + lb) * 4);
    }

    stage(0, 0); cpa_commit();

    for (int c = 0; c < 32; c++) {
        cpa_wait<0>();                 // my chunk-c copies done
        __syncthreads();               // publish all threads' data; gate buffer reuse
        if (c < 31) { stage(c + 1, (c + 1) & 1); cpa_commit(); }

        const uint32_t aBase = sb + (uint32_t)(2 * (c & 1)) * ABUF * 4;
        const uint32_t bBase = aBase + ABUF * 4;
#pragma unroll
        for (int kc = 0; kc < 4; kc++) {
            const uint32_t kkB = kc * 32;
            uint32_t a[4][4];
#pragma unroll
            for (int mi = 0; mi < 4; mi++)
                ldsm_x4(a[mi], aBase + aOff[mi] + kkB);
#pragma unroll
            for (int pr = 0; pr < 4; pr++) {
                uint32_t bfr[4];
                ldsm_x4(bfr, bBase + bOff[pr] + kkB);
#pragma unroll
                for (int mi = 0; mi < 4; mi++) {
                    mma_tf32(acc[mi][pr * 2],     a[mi], bfr);
                    mma_tf32(acc[mi][pr * 2 + 1], a[mi], bfr + 2);
                }
            }
        }
    }

#pragma unroll
    for (int mi = 0; mi < 4; mi++) {
        int r0 = m0 + wm * 64 + mi * 16 + g;
#pragma unroll
        for (int nt = 0; nt < 8; nt++) {
            int col = c0 + wn * 64 + nt * 8 + 2 * tg;
            float2 v0, v1;
            if (ROUND) {
                v0 = make_float2(rtf(acc[mi][nt][0]), rtf(acc[mi][nt][1]));
                v1 = make_float2(rtf(acc[mi][nt][2]), rtf(acc[mi][nt][3]));
            } else {
                v0 = make_float2(acc[mi][nt][0], acc[mi][nt][1]);
                v1 = make_float2(acc[mi][nt][2], acc[mi][nt][3]);
            }
            *reinterpret_cast<float2*>(&C[(size_t)r0 * ldc + col])       = v0;
            *reinterpret_cast<float2*>(&C[(size_t)(r0 + 8) * ldc + col]) = v1;
        }
    }
}

__global__ __launch_bounds__(128) void qkv_mma() {
    int nb = blockIdx.x;
    int m0 = blockIdx.y * 128;
    if (nb < 8)
        gemm_tile<true>(g_X, g_WT, g_Q, EMB, m0, nb * 128, nb * 128);
    else if (nb < 10)
        gemm_tile<true>(g_X, g_WT, g_K, KVW, m0, nb * 128, (nb - 8) * 128);
    else
        gemm_tile<true>(g_X, g_WT, g_V, KVW, m0, nb * 128, (nb - 10) * 128);
}

__global__ __launch_bounds__(128) void oproj_mma(float* __restrict__ out) {
    gemm_tile<false>(g_O, g_WoT, out, EMB, blockIdx.y * 128, blockIdx.x * 128, blockIdx.x * 128);
}

// ================= flash attention: BM=128, 8 warps x 16 rows ================
#define FST  68
#define PS_SZ (128 * FST)             // 8704 floats
#define TBUF  (64 * FST)              // 4352 floats
#define FA_SMEM ((PS_SZ + 4 * TBUF) * 4)   // 104448 B

__global__ __launch_bounds__(256, 2) void flash_mma()
{
    extern __shared__ float fsm[];
    float* Ps = fsm;                  // [128][FST]: Q staging, then P
    const uint32_t sb   = smem_u32(fsm);
    const uint32_t sbK0 = sb + PS_SZ * 4;
    const uint32_t sbV0 = sbK0 + 2 * TBUF * 4;

    const int tid  = threadIdx.x;
    const int lane = tid & 31;
    const int w    = tid >> 5;
    const int g    = lane >> 2;
    const int tg   = lane & 3;
    const int wr   = w * 16;

    const int gh  = blockIdx.x;
    const int qb  = (int)gridDim.y - 1 - blockIdx.y;
    const int grp = gh & 1;
    const int h   = gh >> 1;
    const int kvh = h >> 2;

    const float* Qp  = g_Q + grp * EMB + h * HD;
    const float* Kp  = g_K + grp * KVW + kvh * HD;
    const float* VTp = g_VT + (size_t)((grp * 4 + kvh) * 64) * S_LEN;
    float*       Op  = g_O + grp * EMB + h * HD;

    const int q0 = qb * 128;
    const float SC = 0.125f * 1.4426950408889634f;

    // ---- stage Q * SC (tf32-rounded) ----
    {
        const int row = tid >> 4;
        const int c   = (tid & 15) * 4;
#pragma unroll
        for (int p = 0; p < 8; p++) {
            int r = row + p * 16;
            float4 qv = *reinterpret_cast<const float4*>(&Qp[(size_t)(q0 + r) * ROWQ + c]);
            float* d = &Ps[r * FST + c];
            d[0] = rtf(qv.x * SC); d[1] = rtf(qv.y * SC);
            d[2] = rtf(qv.z * SC); d[3] = rtf(qv.w * SC);
        }
    }
    __syncthreads();

    const int laA = ldsmA_off(lane, FST);
    const int laB = ldsmB_off(lane, FST);
    const uint32_t pOff = (uint32_t)((wr * FST + laA) * 4);
    uint32_t bOff[4];
#pragma unroll
    for (int pr = 0; pr < 4; pr++)
        bOff[pr] = (uint32_t)((pr * 16 * FST + laB) * 4);

    // ---- hoist Q fragments ----
    uint32_t aq[8][4];
#pragma unroll
    for (int kc = 0; kc < 8; kc++)
        ldsm_x4(aq[kc], sb + pOff + kc * 32);
    __syncthreads();   // Ps now free for P

    // ---- K/VT staging ----
    const int srow = tid >> 4;
    const int sq   = (tid & 15) * 4;
    auto stage_kv = [&](int kb, int buf) {
        const int kn = kb * 64;
        const uint32_t kBase = sbK0 + (uint32_t)buf * TBUF * 4;
        const uint32_t vBase = sbV0 + (uint32_t)buf * TBUF * 4;
#pragma unroll
        for (int p = 0; p < 4; p++) {
            int r = srow + p * 16;
            cpa16(kBase + (uint32_t)(r * FST + sq) * 4, &Kp[(size_t)(kn + r) * ROWK + sq]);
            cpa16(vBase + (uint32_t)(r * FST + sq) * 4, &VTp[(size_t)r * S_LEN + kn + sq]);
        }
    };

    float m_i[2] = {-1e30f, -1e30f};
    float l_i[2] = {0.0f, 0.0f};
    float o[8][4];
#pragma unroll
    for (int nt = 0; nt < 8; nt++)
#pragma unroll
        for (int j = 0; j < 4; j++) o[nt][j] = 0.0f;

    const int kbmax = 2 * qb + 1;
    stage_kv(0, 0);
    cpa_commit();

    for (int kb = 0; kb <= kbmax; kb++) {
        const int kn  = kb * 64;
        const int buf = kb & 1;

        cpa_wait<0>();                 // my copies of buffer kb done
        __syncthreads();               // publish all; gate reuse of buf^1
        if (kb < kbmax) { stage_kv(kb + 1, buf ^ 1); cpa_commit(); }

        const uint32_t kBase = sbK0 + (uint32_t)buf * TBUF * 4;
        const uint32_t vBase = sbV0 + (uint32_t)buf * TBUF * 4;

        // ---- S = (Q*SC) K^T ----
        float s[8][4];
#pragma unroll
        for (int nt = 0; nt < 8; nt++)
#pragma unroll
            for (int j = 0; j < 4; j++) s[nt][j] = 0.0f;

#pragma unroll
        for (int kc = 0; kc < 8; kc++) {
            const uint32_t kkB = kc * 32;
#pragma unroll
            for (int pr = 0; pr < 4; pr++) {
                uint32_t bfr[4];
                ldsm_x4(bfr, kBase + bOff[pr] + kkB);
                mma_tf32(s[pr * 2],     aq[kc], bfr);
                mma_tf32(s[pr * 2 + 1], aq[kc], bfr + 2);
            }
        }

        // ---- online softmax with lazy rescale ----
        const bool diag = (kn + 63 > q0);
        {
            const int r0 = q0 + wr + g;
            const int r1 = r0 + 8;
            float mx0 = -1e30f, mx1 = -1e30f;
#pragma unroll
            for (int nt = 0; nt < 8; nt++) {
                int cc = kn + nt * 8 + 2 * tg;
                float v0 = s[nt][0], v1 = s[nt][1], v2 = s[nt][2], v3 = s[nt][3];
                if (diag) {
                    if (cc > r0)     v0 = -1e30f;
                    if (cc + 1 > r0) v1 = -1e30f;
                    if (cc > r1)     v2 = -1e30f;
                    if (cc + 1 > r1) v3 = -1e30f;
                }
                s[nt][0] = v0; s[nt][1] = v1; s[nt][2] = v2; s[nt][3] = v3;
                mx0 = fmaxf(mx0, fmaxf(v0, v1));
                mx1 = fmaxf(mx1, fmaxf(v2, v3));
            }
            mx0 = fmaxf(mx0, __shfl_xor_sync(0xffffffffu, mx0, 1));
            mx0 = fmaxf(mx0, __shfl_xor_sync(0xffffffffu, mx0, 2));
            mx1 = fmaxf(mx1, __shfl_xor_sync(0xffffffffu, mx1, 1));
            mx1 = fmaxf(mx1, __shfl_xor_sync(0xffffffffu, mx1, 2));

            const float mn0 = fmaxf(m_i[0], mx0), mn1 = fmaxf(m_i[1], mx1);
            // lazy rescale: only if some lane's running max advanced
            if (__any_sync(0xffffffffu, (mn0 > m_i[0]) || (mn1 > m_i[1]))) {
                float al0 = exp2f(m_i[0] - mn0), al1 = exp2f(m_i[1] - mn1);
                l_i[0] *= al0; l_i[1] *= al1;
                m_i[0] = mn0;  m_i[1] = mn1;
#pragma unroll
                for (int nt = 0; nt < 8; nt++) {
                    o[nt][0] *= al0; o[nt][1] *= al0;
                    o[nt][2] *= al1; o[nt][3] *= al1;
                }
            }

            float ps0 = 0.0f, ps1 = 0.0f;
            const int pr0 = (wr + g) * FST;
            const int pr1 = pr0 + 8 * FST;
#pragma unroll
            for (int nt = 0; nt < 8; nt++) {
                float p0 = exp2f(s[nt][0] - m_i[0]);
                float p1 = exp2f(s[nt][1] - m_i[0]);
                float p2 = exp2f(s[nt][2] - m_i[1]);
                float p3 = exp2f(s[nt][3] - m_i[1]);
                ps0 += p0 + p1; ps1 += p2 + p3;
                int cc = nt * 8 + 2 * tg;
                Ps[pr0 + cc]     = __uint_as_float(f2tf32(p0));
                Ps[pr0 + cc + 1] = __uint_as_float(f2tf32(p1));
                Ps[pr1 + cc]     = __uint_as_float(f2tf32(p2));
                Ps[pr1 + cc + 1] = __uint_as_float(f2tf32(p3));
            }
            ps0 += __shfl_xor_sync(0xffffffffu, ps0, 1);
            ps0 += __shfl_xor_sync(0xffffffffu, ps0, 2);
            ps1 += __shfl_xor_sync(0xffffffffu, ps1, 1);
            ps1 += __shfl_xor_sync(0xffffffffu, ps1, 2);
            l_i[0] += ps0;
            l_i[1] += ps1;
        }
        __syncwarp();

        // ---- O += P V ----
#pragma unroll
        for (int kc = 0; kc < 8; kc++) {
            const uint32_t kkB = kc * 32;
            uint32_t a[4];
            ldsm_x4(a, sb + pOff + kkB);
#pragma unroll
            for (int pr = 0; pr < 4; pr++) {
                uint32_t bfr[4];
                ldsm_x4(bfr, vBase + bOff[pr] + kkB);
                mma_tf32(o[pr * 2],     a, bfr);
                mma_tf32(o[pr * 2 + 1], a, bfr + 2);
            }
        }
    }

    // ---- epilogue ----
    const float inv0 = 1.0f / l_i[0];
    const float inv1 = 1.0f / l_i[1];
    const size_t row0 = (size_t)(q0 + wr + g) * ROWQ;
    const size_t row1 = row0 + 8 * ROWQ;
#pragma unroll
    for (int nt = 0; nt < 8; nt++) {
        int cc = nt * 8 + 2 * tg;
        *reinterpret_cast<float2*>(&Op[row0 + cc]) =
            make_float2(rtf(o[nt][0] * inv0), rtf(o[nt][1] * inv0));
        *reinterpret_cast<float2*>(&Op[row1 + cc]) =
            make_float2(rtf(o[nt][2] * inv1), rtf(o[nt][3] * inv1));
    }
}

// ================= launch =====================================================
extern "C" void kernel_launch(void* const* d_in, const int* in_sizes, int n_in,
                              void* d_out, int out_size)
{
    const float* x  = (const float*)d_in[0];
    const float* Wq = (const float*)d_in[1];
    const float* Wk = (const float*)d_in[2];
    const float* Wv = (const float*)d_in[3];
    const float* Wo = (const float*)d_in[4];
    float* out = (float*)d_out;

    cudaFuncSetAttribute(flash_mma, cudaFuncAttributeMaxDynamicSharedMemorySize, FA_SMEM);
    cudaFuncSetAttribute(qkv_mma,   cudaFuncAttributeMaxDynamicSharedMemorySize, GEMM_SMEM);
    cudaFuncSetAttribute(oproj_mma, cudaFuncAttributeMaxDynamicSharedMemorySize, GEMM_SMEM);

    round_x<<<MROWS * EMB / (512 * 4), 512>>>(x);
    transpose_all<<<dim3(80, 32), dim3(32, 32)>>>(Wq, Wk, Wv, Wo);

    qkv_mma<<<dim3(12, 32), 128, GEMM_SMEM>>>();
    transpose_v<<<dim3(64, 8), 256>>>();
    flash_mma<<<dim3(32, 16), 256, FA_SMEM>>>();
    oproj_mma<<<dim3(8, 32), 128, GEMM_SMEM>>>(out);
}

// round 10
// speedup vs baseline: 1.8452x; 1.8452x over previous
#include <cuda_runtime.h>
#include <cuda_fp16.h>
#include <cstdint>

#define S_LEN  2048
#define G_GRP  2
#define EMB    1024
#define NKV    4
#define HD     64
#define MROWS  (S_LEN * G_GRP)      // 4096
#define KVW    (NKV * HD)           // 256
#define ROWQ   (G_GRP * EMB)        // 2048 (halves)
#define ROWK   (G_GRP * KVW)        // 512  (halves)

// ---------------- scratch (all fp16) ----------------
__device__ __half g_X[MROWS * EMB];
__device__ __half g_Q[MROWS * EMB];                 // pre-scaled by SC
__device__ __half g_K[MROWS * KVW];
__device__ __half g_V[MROWS * KVW];
__device__ __half g_VT[G_GRP * NKV * HD * S_LEN];   // [(grp*4+kvh)*64+d][seq]
__device__ __half g_O[MROWS * EMB];
__device__ __half g_WT[(EMB + 2 * KVW) * EMB];
__device__ __half g_WoT[EMB * EMB];

#define SC_CONST (0.125f * 1.4426950408889634f)

// ================= helpers =================
__device__ __forceinline__ uint32_t smem_u32(const void* p) {
    uint32_t a;
    asm("{ .reg .u64 t; cvta.to.shared.u64 t, %1; cvt.u32.u64 %0, t; }" : "=r"(a) : "l"(p));
    return a;
}
__device__ __forceinline__ void mma_f16(float c[4], const uint32_t a[4], const uint32_t b[2]) {
    asm volatile(
        "mma.sync.aligned.m16n8k16.row.col.f32.f16.f16.f32 "
        "{%0,%1,%2,%3}, {%4,%5,%6,%7}, {%8,%9}, {%0,%1,%2,%3};"
        : "+f"(c[0]), "+f"(c[1]), "+f"(c[2]), "+f"(c[3])
        : "r"(a[0]), "r"(a[1]), "r"(a[2]), "r"(a[3]), "r"(b[0]), "r"(b[1]));
}
__device__ __forceinline__ void ldsm_x4(uint32_t r[4], uint32_t addr) {
    asm volatile("ldmatrix.sync.aligned.m8n8.x4.shared.b16 {%0,%1,%2,%3}, [%4];"
        : "=r"(r[0]), "=r"(r[1]), "=r"(r[2]), "=r"(r[3]) : "r"(addr));
}
// half-unit offsets; stride in halves. A: 16 rows x k16 (mats: r0k0,r8k0,r0k8,r8k8)
__device__ __forceinline__ int ldsmA_off(int lane, int stride) {
    return ((lane & 7) + ((lane >> 3) & 1) * 8) * stride + ((lane >> 4) & 1) * 8;
}
// B: 16 n-rows x k16 (mats: n0k0,n0k8,n8k0,n8k8)
__device__ __forceinline__ int ldsmB_off(int lane, int stride) {
    return ((lane & 7) + ((lane >> 4) & 1) * 8) * stride + ((lane >> 3) & 1) * 8;
}
__device__ __forceinline__ void cpa16(uint32_t dst, const void* src) {
    asm volatile("cp.async.cg.shared.global [%0], [%1], 16;" :: "r"(dst), "l"(src));
}
__device__ __forceinline__ void cpa_commit() { asm volatile("cp.async.commit_group;"); }
template <int N>
__device__ __forceinline__ void cpa_wait() { asm volatile("cp.async.wait_group %0;" :: "n"(N)); }

// ================= producer-side prep =================
__global__ __launch_bounds__(1024) void transpose_all(
    const float* __restrict__ Wq, const float* __restrict__ Wk,
    const float* __restrict__ Wv, const float* __restrict__ Wo)
{
    __shared__ float t[32][33];
    const int bx = blockIdx.x;
    const float* W; __half* WT; int N; int nb;
    if (bx < 32)      { W = Wq; WT = g_WT;                               N = EMB; nb = bx; }
    else if (bx < 40) { W = Wk; WT = g_WT + (size_t)EMB * EMB;           N = KVW; nb = bx - 32; }
    else if (bx < 48) { W = Wv; WT = g_WT + (size_t)(EMB + KVW) * EMB;   N = KVW; nb = bx - 40; }
    else              { W = Wo; WT = g_WoT;                              N = EMB; nb = bx - 48; }

    int n = nb * 32 + threadIdx.x;
    int k = blockIdx.y * 32 + threadIdx.y;
    t[threadIdx.y][threadIdx.x] = W[(size_t)k * N + n];
    __syncthreads();
    int n2 = nb * 32 + threadIdx.y;
    int k2 = blockIdx.y * 32 + threadIdx.x;
    WT[(size_t)n2 * EMB + k2] = __float2half(t[threadIdx.x][threadIdx.y]);
}

__global__ __launch_bounds__(512) void round_x(const float* __restrict__ x) {
    size_t i = (size_t)blockIdx.x * 512 + threadIdx.x;   // 8 floats per thread
    const float4* src = reinterpret_cast<const float4*>(x) + 2 * i;
    float4 v0 = src[0], v1 = src[1];
    __half2* dst = reinterpret_cast<__half2*>(g_X) + 4 * i;
    dst[0] = __floats2half2_rn(v0.x, v0.y);
    dst[1] = __floats2half2_rn(v0.z, v0.w);
    dst[2] = __floats2half2_rn(v1.x, v1.y);
    dst[3] = __floats2half2_rn(v1.z, v1.w);
}

// coalesced V transpose (half): g_V[m][c] -> g_VT[(m&1)*256 + c][m>>1]
__global__ __launch_bounds__(256) void transpose_v() {
    __shared__ __half t[64][33];
    const int mt = blockIdx.x;
    const int ct = blockIdx.y;
    const int tx = threadIdx.x & 31;
    const int ty = threadIdx.x >> 5;
#pragma unroll
    for (int k = 0; k < 8; k++) {
        int ml = ty + k * 8;
        t[ml][tx] = g_V[(size_t)(mt * 64 + ml) * KVW + ct * 32 + tx];
    }
    __syncthreads();
#pragma unroll
    for (int k = 0; k < 8; k++) {
        int rs  = ty + k * 8;
        int grp = rs >> 5, c = rs & 31;
        g_VT[(size_t)(grp * 256 + ct * 32 + c) * S_LEN + mt * 32 + tx] = t[grp + 2 * tx][c];
    }
}

// ================= fp16 mma GEMM: 128x128 CTA, 64x64 warp tile ==============
#define AST 72                        // halves; 144 B stride -> LDSM conflict-free
#define ABUF_H (128 * AST)            // halves per buffer
#define GEMM_SMEM (4 * ABUF_H * 2)    // 73728 B

// OM: 0 = fp32 out, 1 = half out, 2 = half out * SC
template <int OM>
__device__ __forceinline__ void gemm_tile(
    const __half* __restrict__ A, const __half* __restrict__ BT,
    void* __restrict__ Cv, int ldc, int m0, int n0bt, int c0)
{
    extern __shared__ __half hsm[];
    const uint32_t sb = smem_u32(hsm);

    const int tid  = threadIdx.x;      // 0..127
    const int lane = tid & 31;
    const int wid  = tid >> 5;
    const int wm   = wid >> 1;
    const int wn   = wid & 1;
    const int g    = lane >> 2;
    const int tg   = lane & 3;

    float acc[4][8][4];
#pragma unroll
    for (int mi = 0; mi < 4; mi++)
#pragma unroll
        for (int nt = 0; nt < 8; nt++)
#pragma unroll
            for (int j = 0; j < 4; j++) acc[mi][nt][j] = 0.0f;

    const int row = tid >> 3;          // 0..15
    const int q   = (tid & 7) * 8;     // halves

    auto stage = [&](int c, int buf) {
        const int k0 = c * 64;
        const uint32_t aBase = sb + (uint32_t)(2 * buf) * ABUF_H * 2;
        const uint32_t bBase = aBase + ABUF_H * 2;
#pragma unroll
        for (int t = 0; t < 8; t++) {
            int r = row + t * 16;
            cpa16(aBase + (uint32_t)(r * AST + q) * 2, &A [(size_t)(m0 + r) * EMB + k0 + q]);
            cpa16(bBase + (uint32_t)(r * AST + q) * 2, &BT[(size_t)(n0bt + r) * EMB + k0 + q]);
        }
    };

    uint32_t aOff[4], bOff[4];
    {
        const int la = ldsmA_off(lane, AST);
        const int lb = ldsmB_off(lane, AST);
#pragma unroll
        for (int mi = 0; mi < 4; mi++)
            aOff[mi] = (uint32_t)(((wm * 64 + mi * 16) * AST + la) * 2);
#pragma unroll
        for (int pr = 0; pr < 4; pr++)
            bOff[pr] = (uint32_t)(((wn * 64 + pr * 16) * AST + lb) * 2);
    }

    stage(0, 0); cpa_commit();

    for (int c = 0; c < 16; c++) {     // K = 1024 / 64
        if (c < 15) { stage(c + 1, (c + 1) & 1); cpa_commit(); cpa_wait<1>(); }
        else        { cpa_wait<0>(); }
        __syncthreads();

        const uint32_t aBase = sb + (uint32_t)(2 * (c & 1)) * ABUF_H * 2;
        const uint32_t bBase = aBase + ABUF_H * 2;
#pragma unroll
        for (int kc = 0; kc < 4; kc++) {
            const uint32_t kkB = kc * 32;    // 16 halves
            uint32_t a[4][4];
#pragma unroll
            for (int mi = 0; mi < 4; mi++)
                ldsm_x4(a[mi], aBase + aOff[mi] + kkB);
#pragma unroll
            for (int pr = 0; pr < 4; pr++) {
                uint32_t bfr[4];
                ldsm_x4(bfr, bBase + bOff[pr] + kkB);
#pragma unroll
                for (int mi = 0; mi < 4; mi++) {
                    mma_f16(acc[mi][pr * 2],     a[mi], bfr);
                    mma_f16(acc[mi][pr * 2 + 1], a[mi], bfr + 2);
                }
            }
        }
        __syncthreads();
    }

#pragma unroll
    for (int mi = 0; mi < 4; mi++) {
        int r0 = m0 + wm * 64 + mi * 16 + g;
#pragma unroll
        for (int nt = 0; nt < 8; nt++) {
            int col = c0 + wn * 64 + nt * 8 + 2 * tg;
            if (OM == 0) {
                float* C = (float*)Cv;
                *reinterpret_cast<float2*>(&C[(size_t)r0 * ldc + col]) =
                    make_float2(acc[mi][nt][0], acc[mi][nt][1]);
                *reinterpret_cast<float2*>(&C[(size_t)(r0 + 8) * ldc + col]) =
                    make_float2(acc[mi][nt][2], acc[mi][nt][3]);
            } else {
                const float m = (OM == 2) ? SC_CONST : 1.0f;
                __half* C = (__half*)Cv;
                *reinterpret_cast<__half2*>(&C[(size_t)r0 * ldc + col]) =
                    __floats2half2_rn(acc[mi][nt][0] * m, acc[mi][nt][1] * m);
                *reinterpret_cast<__half2*>(&C[(size_t)(r0 + 8) * ldc + col]) =
                    __floats2half2_rn(acc[mi][nt][2] * m, acc[mi][nt][3] * m);
            }
        }
    }
}

__global__ __launch_bounds__(128) void qkv_mma() {
    int nb = blockIdx.x;
    int m0 = blockIdx.y * 128;
    if (nb < 8)
        gemm_tile<2>(g_X, g_WT, g_Q, EMB, m0, nb * 128, nb * 128);
    else if (nb < 10)
        gemm_tile<1>(g_X, g_WT, g_K, KVW, m0, nb * 128, (nb - 8) * 128);
    else
        gemm_tile<1>(g_X, g_WT, g_V, KVW, m0, nb * 128, (nb - 10) * 128);
}

__global__ __launch_bounds__(128) void oproj_mma(float* __restrict__ out) {
    gemm_tile<0>(g_O, g_WoT, out, EMB, blockIdx.y * 128, blockIdx.x * 128, blockIdx.x * 128);
}

// ================= flash attention: fp16 mma, BM=128, 8 warps ================
#define FST  72
#define PS_H (128 * FST)              // halves
#define TB_H (64 * FST)               // halves
#define FA_SMEM ((PS_H + 4 * TB_H) * 2)   // 55296 B

__global__ __launch_bounds__(256, 2) void flash_mma()
{
    extern __shared__ __half fsm[];
    __half* Ps = fsm;                 // [128][FST]: Q staging, then P
    const uint32_t sb   = smem_u32(fsm);
    const uint32_t sbK0 = sb + PS_H * 2;
    const uint32_t sbV0 = sbK0 + 2 * TB_H * 2;

    const int tid  = threadIdx.x;
    const int lane = tid & 31;
    const int w    = tid >> 5;
    const int g    = lane >> 2;
    const int tg   = lane & 3;
    const int wr   = w * 16;

    const int gh  = blockIdx.x;
    const int qb  = (int)gridDim.y - 1 - blockIdx.y;
    const int grp = gh & 1;
    const int h   = gh >> 1;
    const int kvh = h >> 2;

    const __half* Qp  = g_Q + grp * EMB + h * HD;
    const __half* Kp  = g_K + grp * KVW + kvh * HD;
    const __half* VTp = g_VT + (size_t)((grp * 4 + kvh) * 64) * S_LEN;
    __half*       Op  = g_O + grp * EMB + h * HD;

    const int q0 = qb * 128;

    const int laA = ldsmA_off(lane, FST);
    const int laB = ldsmB_off(lane, FST);
    const uint32_t pOff = (uint32_t)((wr * FST + laA) * 2);
    uint32_t bOff[4];
#pragma unroll
    for (int pr = 0; pr < 4; pr++)
        bOff[pr] = (uint32_t)((pr * 16 * FST + laB) * 2);

    // ---- stage Q (pre-scaled in gmem) via cp.async ----
    {
        const int r0s = tid >> 3;          // 0..31
        const int qs  = (tid & 7) * 8;
#pragma unroll
        for (int p = 0; p < 4; p++) {
            int r = r0s + p * 32;
            cpa16(sb + (uint32_t)(r * FST + qs) * 2, &Qp[(size_t)(q0 + r) * ROWQ + qs]);
        }
        cpa_commit();
    }

    // ---- K/VT staging ----
    const int srow = tid >> 3;             // 0..31
    const int sq   = (tid & 7) * 8;
    auto stage_kv = [&](int kb, int buf) {
        const int kn = kb * 64;
        const uint32_t kBase = sbK0 + (uint32_t)buf * TB_H * 2;
        const uint32_t vBase = sbV0 + (uint32_t)buf * TB_H * 2;
#pragma unroll
        for (int p = 0; p < 2; p++) {
            int r = srow + p * 32;
            cpa16(kBase + (uint32_t)(r * FST + sq) * 2, &Kp[(size_t)(kn + r) * ROWK + sq]);
            cpa16(vBase + (uint32_t)(r * FST + sq) * 2, &VTp[(size_t)r * S_LEN + kn + sq]);
        }
    };

    stage_kv(0, 0);
    cpa_commit();
    cpa_wait<1>();                        // Q group done
    __syncthreads();

    // ---- hoist Q fragments (4 k-chunks of 16) ----
    uint32_t aq[4][4];
#pragma unroll
    for (int kc = 0; kc < 4; kc++)
        ldsm_x4(aq[kc], sb + pOff + kc * 32);
    __syncthreads();                      // Ps now free for P

    float m_i[2] = {-1e30f, -1e30f};
    float l_i[2] = {0.0f, 0.0f};
    float o[8][4];
#pragma unroll
    for (int nt = 0; nt < 8; nt++)
#pragma unroll
        for (int j = 0; j < 4; j++) o[nt][j] = 0.0f;

    const int kbmax = 2 * qb + 1;

    for (int kb = 0; kb <= kbmax; kb++) {
        const int kn  = kb * 64;
        const int buf = kb & 1;
        if (kb < kbmax) {
            stage_kv(kb + 1, buf ^ 1);
            cpa_commit();
            cpa_wait<1>();
        } else {
            cpa_wait<0>();
        }
        __syncthreads();

        const uint32_t kBase = sbK0 + (uint32_t)buf * TB_H * 2;
        const uint32_t vBase = sbV0 + (uint32_t)buf * TB_H * 2;

        // ---- S = (Q*SC) K^T ----
        float s[8][4];
#pragma unroll
        for (int nt = 0; nt < 8; nt++)
#pragma unroll
            for (int j = 0; j < 4; j++) s[nt][j] = 0.0f;

#pragma unroll
        for (int kc = 0; kc < 4; kc++) {
            const uint32_t kkB = kc * 32;
#pragma unroll
            for (int pr = 0; pr < 4; pr++) {
                uint32_t bfr[4];
                ldsm_x4(bfr, kBase + bOff[pr] + kkB);
                mma_f16(s[pr * 2],     aq[kc], bfr);
                mma_f16(s[pr * 2 + 1], aq[kc], bfr + 2);
            }
        }

        // ---- online softmax (base-2) ----
        const bool diag = (kn + 63 > q0);
        {
            const int r0 = q0 + wr + g;
            const int r1 = r0 + 8;
            float mx0 = -1e30f, mx1 = -1e30f;
#pragma unroll
            for (int nt = 0; nt < 8; nt++) {
                int cc = kn + nt * 8 + 2 * tg;
                float v0 = s[nt][0], v1 = s[nt][1], v2 = s[nt][2], v3 = s[nt][3];
                if (diag) {
                    if (cc > r0)     v0 = -1e30f;
                    if (cc + 1 > r0) v1 = -1e30f;
                    if (cc > r1)     v2 = -1e30f;
                    if (cc + 1 > r1) v3 = -1e30f;
                }
                s[nt][0] = v0; s[nt][1] = v1; s[nt][2] = v2; s[nt][3] = v3;
                mx0 = fmaxf(mx0, fmaxf(v0, v1));
                mx1 = fmaxf(mx1, fmaxf(v2, v3));
            }
            mx0 = fmaxf(mx0, __shfl_xor_sync(0xffffffffu, mx0, 1));
            mx0 = fmaxf(mx0, __shfl_xor_sync(0xffffffffu, mx0, 2));
            mx1 = fmaxf(mx1, __shfl_xor_sync(0xffffffffu, mx1, 1));
            mx1 = fmaxf(mx1, __shfl_xor_sync(0xffffffffu, mx1, 2));

            float mn0 = fmaxf(m_i[0], mx0), mn1 = fmaxf(m_i[1], mx1);
            float al0 = exp2f(m_i[0] - mn0), al1 = exp2f(m_i[1] - mn1);
            float ps0 = 0.0f, ps1 = 0.0f;
            const int pr0 = (wr + g) * FST;
            const int pr1 = pr0 + 8 * FST;
#pragma unroll
            for (int nt = 0; nt < 8; nt++) {
                float p0 = exp2f(s[nt][0] - mn0);
                float p1 = exp2f(s[nt][1] - mn0);
                float p2 = exp2f(s[nt][2] - mn1);
                float p3 = exp2f(s[nt][3] - mn1);
                ps0 += p0 + p1; ps1 += p2 + p3;
                int cc = nt * 8 + 2 * tg;
                *reinterpret_cast<__half2*>(&Ps[pr0 + cc]) = __floats2half2_rn(p0, p1);
                *reinterpret_cast<__half2*>(&Ps[pr1 + cc]) = __floats2half2_rn(p2, p3);
                o[nt][0] *= al0; o[nt][1] *= al0;
                o[nt][2] *= al1; o[nt][3] *= al1;
            }
            ps0 += __shfl_xor_sync(0xffffffffu, ps0, 1);
            ps0 += __shfl_xor_sync(0xffffffffu, ps0, 2);
            ps1 += __shfl_xor_sync(0xffffffffu, ps1, 1);
            ps1 += __shfl_xor_sync(0xffffffffu, ps1, 2);
            l_i[0] = l_i[0] * al0 + ps0;
            l_i[1] = l_i[1] * al1 + ps1;
            m_i[0] = mn0; m_i[1] = mn1;
        }
        __syncwarp();

        // ---- O += P V ----
#pragma unroll
        for (int kc = 0; kc < 4; kc++) {
            const uint32_t kkB = kc * 32;
            uint32_t a[4];
            ldsm_x4(a, sb + pOff + kkB);
#pragma unroll
            for (int pr = 0; pr < 4; pr++) {
                uint32_t bfr[4];
                ldsm_x4(bfr, vBase + bOff[pr] + kkB);
                mma_f16(o[pr * 2],     a, bfr);
                mma_f16(o[pr * 2 + 1], a, bfr + 2);
            }
        }
        __syncthreads();
    }

    // ---- epilogue: normalize, write g_O (half) ----
    const float inv0 = 1.0f / l_i[0];
    const float inv1 = 1.0f / l_i[1];
    const size_t row0 = (size_t)(q0 + wr + g) * ROWQ;
    const size_t row1 = row0 + 8 * ROWQ;
#pragma unroll
    for (int nt = 0; nt < 8; nt++) {
        int cc = nt * 8 + 2 * tg;
        *reinterpret_cast<__half2*>(&Op[row0 + cc]) =
            __floats2half2_rn(o[nt][0] * inv0, o[nt][1] * inv0);
        *reinterpret_cast<__half2*>(&Op[row1 + cc]) =
            __floats2half2_rn(o[nt][2] * inv1, o[nt][3] * inv1);
    }
}

// ================= launch =====================================================
extern "C" void kernel_launch(void* const* d_in, const int* in_sizes, int n_in,
                              void* d_out, int out_size)
{
    const float* x  = (const float*)d_in[0];
    const float* Wq = (const float*)d_in[1];
    const float* Wk = (const float*)d_in[2];
    const float* Wv = (const float*)d_in[3];
    const float* Wo = (const float*)d_in[4];
    float* out = (float*)d_out;

    cudaFuncSetAttribute(flash_mma, cudaFuncAttributeMaxDynamicSharedMemorySize, FA_SMEM);
    cudaFuncSetAttribute(qkv_mma,   cudaFuncAttributeMaxDynamicSharedMemorySize, GEMM_SMEM);
    cudaFuncSetAttribute(oproj_mma, cudaFuncAttributeMaxDynamicSharedMemorySize, GEMM_SMEM);

    round_x<<<MROWS * EMB / (512 * 8), 512>>>(x);
    transpose_all<<<dim3(80, 32), dim3(32, 32)>>>(Wq, Wk, Wv, Wo);

    qkv_mma<<<dim3(12, 32), 128, GEMM_SMEM>>>();
    transpose_v<<<dim3(64, 8), 256>>>();
    flash_mma<<<dim3(32, 16), 256, FA_SMEM>>>();
    oproj_mma<<<dim3(8, 32), 128, GEMM_SMEM>>>(out);
}

// round 11
// speedup vs baseline: 2.0816x; 1.1281x over previous
#include <cuda_runtime.h>
#include <cuda_fp16.h>
#include <cstdint>

#define S_LEN  2048
#define G_GRP  2
#define EMB    1024
#define NKV    4
#define HD     64
#define MROWS  (S_LEN * G_GRP)      // 4096
#define KVW    (NKV * HD)           // 256
#define ROWQ   (G_GRP * EMB)        // 2048 (halves)
#define ROWK   (G_GRP * KVW)        // 512  (halves)

// ---------------- scratch (all fp16) ----------------
__device__ __half g_X[MROWS * EMB];
__device__ __half g_Q[MROWS * EMB];                 // pre-scaled by SC
__device__ __half g_K[MROWS * KVW];
__device__ __half g_V[MROWS * KVW];
__device__ __half g_VT[G_GRP * NKV * HD * S_LEN];   // [(grp*4+kvh)*64+d][seq]
__device__ __half g_O[MROWS * EMB];
__device__ __half g_WT[(EMB + 2 * KVW) * EMB];
__device__ __half g_WoT[EMB * EMB];

#define SC_CONST (0.125f * 1.4426950408889634f)

// ================= helpers =================
__device__ __forceinline__ uint32_t smem_u32(const void* p) {
    uint32_t a;
    asm("{ .reg .u64 t; cvta.to.shared.u64 t, %1; cvt.u32.u64 %0, t; }" : "=r"(a) : "l"(p));
    return a;
}
__device__ __forceinline__ void mma_f16(float c[4], const uint32_t a[4], const uint32_t b[2]) {
    asm volatile(
        "mma.sync.aligned.m16n8k16.row.col.f32.f16.f16.f32 "
        "{%0,%1,%2,%3}, {%4,%5,%6,%7}, {%8,%9}, {%0,%1,%2,%3};"
        : "+f"(c[0]), "+f"(c[1]), "+f"(c[2]), "+f"(c[3])
        : "r"(a[0]), "r"(a[1]), "r"(a[2]), "r"(a[3]), "r"(b[0]), "r"(b[1]));
}
__device__ __forceinline__ void ldsm_x4(uint32_t r[4], uint32_t addr) {
    asm volatile("ldmatrix.sync.aligned.m8n8.x4.shared.b16 {%0,%1,%2,%3}, [%4];"
        : "=r"(r[0]), "=r"(r[1]), "=r"(r[2]), "=r"(r[3]) : "r"(addr));
}
__device__ __forceinline__ int ldsmA_off(int lane, int stride) {
    return ((lane & 7) + ((lane >> 3) & 1) * 8) * stride + ((lane >> 4) & 1) * 8;
}
__device__ __forceinline__ int ldsmB_off(int lane, int stride) {
    return ((lane & 7) + ((lane >> 4) & 1) * 8) * stride + ((lane >> 3) & 1) * 8;
}
__device__ __forceinline__ void cpa16(uint32_t dst, const void* src) {
    asm volatile("cp.async.cg.shared.global [%0], [%1], 16;" :: "r"(dst), "l"(src));
}
__device__ __forceinline__ void cpa_commit() { asm volatile("cp.async.commit_group;"); }
template <int N>
__device__ __forceinline__ void cpa_wait() { asm volatile("cp.async.wait_group %0;" :: "n"(N)); }

// ================= fused prep: X round + all weight transposes ===============
// blocks [0, 2048): convert X to half (8 floats/thread)
// blocks [2048, 4608): 32x32 transpose tiles over Wq/Wk/Wv/Wo
__global__ __launch_bounds__(256) void prep_all(
    const float* __restrict__ x,
    const float* __restrict__ Wq, const float* __restrict__ Wk,
    const float* __restrict__ Wv, const float* __restrict__ Wo)
{
    __shared__ float t[32][33];
    const int b = blockIdx.x;
    if (b < 2048) {
        size_t i = (size_t)b * 256 + threadIdx.x;   // 8 floats per thread
        const float4* src = reinterpret_cast<const float4*>(x) + 2 * i;
        float4 v0 = src[0], v1 = src[1];
        __half2* dst = reinterpret_cast<__half2*>(g_X) + 4 * i;
        dst[0] = __floats2half2_rn(v0.x, v0.y);
        dst[1] = __floats2half2_rn(v0.z, v0.w);
        dst[2] = __floats2half2_rn(v1.x, v1.y);
        dst[3] = __floats2half2_rn(v1.z, v1.w);
        return;
    }
    const int bb = b - 2048;
    const int bx = bb % 80;
    const int by = bb / 80;
    const float* W; __half* WT; int N; int nb;
    if (bx < 32)      { W = Wq; WT = g_WT;                               N = EMB; nb = bx; }
    else if (bx < 40) { W = Wk; WT = g_WT + (size_t)EMB * EMB;           N = KVW; nb = bx - 32; }
    else if (bx < 48) { W = Wv; WT = g_WT + (size_t)(EMB + KVW) * EMB;   N = KVW; nb = bx - 40; }
    else              { W = Wo; WT = g_WoT;                              N = EMB; nb = bx - 48; }

    const int tx  = threadIdx.x & 31;
    const int ty0 = threadIdx.x >> 5;   // 0..7
#pragma unroll
    for (int r = 0; r < 4; r++) {
        int ty = ty0 + r * 8;
        t[ty][tx] = W[(size_t)(by * 32 + ty) * N + nb * 32 + tx];
    }
    __syncthreads();
#pragma unroll
    for (int r = 0; r < 4; r++) {
        int ty = ty0 + r * 8;
        WT[(size_t)(nb * 32 + ty) * EMB + by * 32 + tx] = __float2half(t[tx][ty]);
    }
}

// coalesced V transpose (half): g_V[m][c] -> g_VT[(m&1)*256 + c][m>>1]
__global__ __launch_bounds__(256) void transpose_v() {
    __shared__ __half t[64][33];
    const int mt = blockIdx.x;
    const int ct = blockIdx.y;
    const int tx = threadIdx.x & 31;
    const int ty = threadIdx.x >> 5;
#pragma unroll
    for (int k = 0; k < 8; k++) {
        int ml = ty + k * 8;
        t[ml][tx] = g_V[(size_t)(mt * 64 + ml) * KVW + ct * 32 + tx];
    }
    __syncthreads();
#pragma unroll
    for (int k = 0; k < 8; k++) {
        int rs  = ty + k * 8;
        int grp = rs >> 5, c = rs & 31;
        g_VT[(size_t)(grp * 256 + ct * 32 + c) * S_LEN + mt * 32 + tx] = t[grp + 2 * tx][c];
    }
}

// ================= fp16 mma GEMM: 128x128 CTA, 64x64 warp tile ==============
#define AST 72
#define ABUF_H (128 * AST)
#define GEMM_SMEM (4 * ABUF_H * 2)    // 73728 B

// OM: 0 = fp32 out, 1 = half out, 2 = half out * SC
template <int OM>
__device__ __forceinline__ void gemm_tile(
    const __half* __restrict__ A, const __half* __restrict__ BT,
    void* __restrict__ Cv, int ldc, int m0, int n0bt, int c0)
{
    extern __shared__ __half hsm[];
    const uint32_t sb = smem_u32(hsm);

    const int tid  = threadIdx.x;
    const int lane = tid & 31;
    const int wid  = tid >> 5;
    const int wm   = wid >> 1;
    const int wn   = wid & 1;
    const int g    = lane >> 2;
    const int tg   = lane & 3;

    float acc[4][8][4];
#pragma unroll
    for (int mi = 0; mi < 4; mi++)
#pragma unroll
        for (int nt = 0; nt < 8; nt++)
#pragma unroll
            for (int j = 0; j < 4; j++) acc[mi][nt][j] = 0.0f;

    const int row = tid >> 3;
    const int q   = (tid & 7) * 8;

    auto stage = [&](int c, int buf) {
        const int k0 = c * 64;
        const uint32_t aBase = sb + (uint32_t)(2 * buf) * ABUF_H * 2;
        const uint32_t bBase = aBase + ABUF_H * 2;
#pragma unroll
        for (int t = 0; t < 8; t++) {
            int r = row + t * 16;
            cpa16(aBase + (uint32_t)(r * AST + q) * 2, &A [(size_t)(m0 + r) * EMB + k0 + q]);
            cpa16(bBase + (uint32_t)(r * AST + q) * 2, &BT[(size_t)(n0bt + r) * EMB + k0 + q]);
        }
    };

    uint32_t aOff[4], bOff[4];
    {
        const int la = ldsmA_off(lane, AST);
        const int lb = ldsmB_off(lane, AST);
#pragma unroll
        for (int mi = 0; mi < 4; mi++)
            aOff[mi] = (uint32_t)(((wm * 64 + mi * 16) * AST + la) * 2);
#pragma unroll
        for (int pr = 0; pr < 4; pr++)
            bOff[pr] = (uint32_t)(((wn * 64 + pr * 16) * AST + lb) * 2);
    }

    stage(0, 0); cpa_commit();

    for (int c = 0; c < 16; c++) {
        if (c < 15) { stage(c + 1, (c + 1) & 1); cpa_commit(); cpa_wait<1>(); }
        else        { cpa_wait<0>(); }
        __syncthreads();

        const uint32_t aBase = sb + (uint32_t)(2 * (c & 1)) * ABUF_H * 2;
        const uint32_t bBase = aBase + ABUF_H * 2;
#pragma unroll
        for (int kc = 0; kc < 4; kc++) {
            const uint32_t kkB = kc * 32;
            uint32_t a[4][4];
#pragma unroll
            for (int mi = 0; mi < 4; mi++)
                ldsm_x4(a[mi], aBase + aOff[mi] + kkB);
#pragma unroll
            for (int pr = 0; pr < 4; pr++) {
                uint32_t bfr[4];
                ldsm_x4(bfr, bBase + bOff[pr] + kkB);
#pragma unroll
                for (int mi = 0; mi < 4; mi++) {
                    mma_f16(acc[mi][pr * 2],     a[mi], bfr);
                    mma_f16(acc[mi][pr * 2 + 1], a[mi], bfr + 2);
                }
            }
        }
        __syncthreads();
    }

#pragma unroll
    for (int mi = 0; mi < 4; mi++) {
        int r0 = m0 + wm * 64 + mi * 16 + g;
#pragma unroll
        for (int nt = 0; nt < 8; nt++) {
            int col = c0 + wn * 64 + nt * 8 + 2 * tg;
            if (OM == 0) {
                float* C = (float*)Cv;
                *reinterpret_cast<float2*>(&C[(size_t)r0 * ldc + col]) =
                    make_float2(acc[mi][nt][0], acc[mi][nt][1]);
                *reinterpret_cast<float2*>(&C[(size_t)(r0 + 8) * ldc + col]) =
                    make_float2(acc[mi][nt][2], acc[mi][nt][3]);
            } else {
                const float m = (OM == 2) ? SC_CONST : 1.0f;
                __half* C = (__half*)Cv;
                *reinterpret_cast<__half2*>(&C[(size_t)r0 * ldc + col]) =
                    __floats2half2_rn(acc[mi][nt][0] * m, acc[mi][nt][1] * m);
                *reinterpret_cast<__half2*>(&C[(size_t)(r0 + 8) * ldc + col]) =
                    __floats2half2_rn(acc[mi][nt][2] * m, acc[mi][nt][3] * m);
            }
        }
    }
}

// qkv: allow 3 CTAs/SM (384 CTAs -> single wave on 148 SMs)
__global__ __launch_bounds__(128, 3) void qkv_mma() {
    int nb = blockIdx.x;
    int m0 = blockIdx.y * 128;
    if (nb < 8)
        gemm_tile<2>(g_X, g_WT, g_Q, EMB, m0, nb * 128, nb * 128);
    else if (nb < 10)
        gemm_tile<1>(g_X, g_WT, g_K, KVW, m0, nb * 128, (nb - 8) * 128);
    else
        gemm_tile<1>(g_X, g_WT, g_V, KVW, m0, nb * 128, (nb - 10) * 128);
}

__global__ __launch_bounds__(128) void oproj_mma(float* __restrict__ out) {
    gemm_tile<0>(g_O, g_WoT, out, EMB, blockIdx.y * 128, blockIdx.x * 128, blockIdx.x * 128);
}

// ================= flash attention: fp16 mma, BM=128, 8 warps ================
#define FST  72
#define PS_H (128 * FST)
#define TB_H (64 * FST)
#define FA_SMEM ((PS_H + 4 * TB_H) * 2)   // 55296 B

__global__ __launch_bounds__(256, 2) void flash_mma()
{
    extern __shared__ __half fsm[];
    __half* Ps = fsm;                 // [128][FST]: Q staging, then P
    const uint32_t sb   = smem_u32(fsm);
    const uint32_t sbK0 = sb + PS_H * 2;
    const uint32_t sbV0 = sbK0 + 2 * TB_H * 2;

    const int tid  = threadIdx.x;
    const int lane = tid & 31;
    const int w    = tid >> 5;
    const int g    = lane >> 2;
    const int tg   = lane & 3;
    const int wr   = w * 16;

    const int gh  = blockIdx.x;
    const int qb  = (int)gridDim.y - 1 - blockIdx.y;
    const int grp = gh & 1;
    const int h   = gh >> 1;
    const int kvh = h >> 2;

    const __half* Qp  = g_Q + grp * EMB + h * HD;
    const __half* Kp  = g_K + grp * KVW + kvh * HD;
    const __half* VTp = g_VT + (size_t)((grp * 4 + kvh) * 64) * S_LEN;
    __half*       Op  = g_O + grp * EMB + h * HD;

    const int q0 = qb * 128;

    const int laA = ldsmA_off(lane, FST);
    const int laB = ldsmB_off(lane, FST);
    const uint32_t pOff = (uint32_t)((wr * FST + laA) * 2);
    uint32_t bOff[4];
#pragma unroll
    for (int pr = 0; pr < 4; pr++)
        bOff[pr] = (uint32_t)((pr * 16 * FST + laB) * 2);

    // ---- stage Q (pre-scaled in gmem) via cp.async ----
    {
        const int r0s = tid >> 3;
        const int qs  = (tid & 7) * 8;
#pragma unroll
        for (int p = 0; p < 4; p++) {
            int r = r0s + p * 32;
            cpa16(sb + (uint32_t)(r * FST + qs) * 2, &Qp[(size_t)(q0 + r) * ROWQ + qs]);
        }
        cpa_commit();
    }

    // ---- K/VT staging ----
    const int srow = tid >> 3;
    const int sq   = (tid & 7) * 8;
    auto stage_kv = [&](int kb, int buf) {
        const int kn = kb * 64;
        const uint32_t kBase = sbK0 + (uint32_t)buf * TB_H * 2;
        const uint32_t vBase = sbV0 + (uint32_t)buf * TB_H * 2;
#pragma unroll
        for (int p = 0; p < 2; p++) {
            int r = srow + p * 32;
            cpa16(kBase + (uint32_t)(r * FST + sq) * 2, &Kp[(size_t)(kn + r) * ROWK + sq]);
            cpa16(vBase + (uint32_t)(r * FST + sq) * 2, &VTp[(size_t)r * S_LEN + kn + sq]);
        }
    };

    stage_kv(0, 0);
    cpa_commit();
    cpa_wait<1>();                        // Q group done
    __syncthreads();

    // ---- hoist Q fragments ----
    uint32_t aq[4][4];
#pragma unroll
    for (int kc = 0; kc < 4; kc++)
        ldsm_x4(aq[kc], sb + pOff + kc * 32);
    __syncthreads();                      // Ps now free for P

    float m_i[2] = {-1e30f, -1e30f};
    float l_i[2] = {0.0f, 0.0f};
    float o[8][4];
#pragma unroll
    for (int nt = 0; nt < 8; nt++)
#pragma unroll
        for (int j = 0; j < 4; j++) o[nt][j] = 0.0f;

    const int kbmax = 2 * qb + 1;

    for (int kb = 0; kb <= kbmax; kb++) {
        const int kn  = kb * 64;
        const int buf = kb & 1;

        // SINGLE barrier per iteration: wait my kb copies, sync (publishes data
        // AND guarantees all warps finished reading buf^1 last iteration), then
        // stage kb+1 into buf^1 while computing on buf.
        cpa_wait<0>();
        __syncthreads();
        if (kb < kbmax) { stage_kv(kb + 1, buf ^ 1); cpa_commit(); }

        const uint32_t kBase = sbK0 + (uint32_t)buf * TB_H * 2;
        const uint32_t vBase = sbV0 + (uint32_t)buf * TB_H * 2;

        // ---- S = (Q*SC) K^T ----
        float s[8][4];
#pragma unroll
        for (int nt = 0; nt < 8; nt++)
#pragma unroll
            for (int j = 0; j < 4; j++) s[nt][j] = 0.0f;

#pragma unroll
        for (int kc = 0; kc < 4; kc++) {
            const uint32_t kkB = kc * 32;
#pragma unroll
            for (int pr = 0; pr < 4; pr++) {
                uint32_t bfr[4];
                ldsm_x4(bfr, kBase + bOff[pr] + kkB);
                mma_f16(s[pr * 2],     aq[kc], bfr);
                mma_f16(s[pr * 2 + 1], aq[kc], bfr + 2);
            }
        }

        // ---- online softmax (base-2) ----
        const bool diag = (kn + 63 > q0);
        {
            const int r0 = q0 + wr + g;
            const int r1 = r0 + 8;
            float mx0 = -1e30f, mx1 = -1e30f;
#pragma unroll
            for (int nt = 0; nt < 8; nt++) {
                int cc = kn + nt * 8 + 2 * tg;
                float v0 = s[nt][0], v1 = s[nt][1], v2 = s[nt][2], v3 = s[nt][3];
                if (diag) {
                    if (cc > r0)     v0 = -1e30f;
                    if (cc + 1 > r0) v1 = -1e30f;
                    if (cc > r1)     v2 = -1e30f;
                    if (cc + 1 > r1) v3 = -1e30f;
                }
                s[nt][0] = v0; s[nt][1] = v1; s[nt][2] = v2; s[nt][3] = v3;
                mx0 = fmaxf(mx0, fmaxf(v0, v1));
                mx1 = fmaxf(mx1, fmaxf(v2, v3));
            }
            mx0 = fmaxf(mx0, __shfl_xor_sync(0xffffffffu, mx0, 1));
            mx0 = fmaxf(mx0, __shfl_xor_sync(0xffffffffu, mx0, 2));
            mx1 = fmaxf(mx1, __shfl_xor_sync(0xffffffffu, mx1, 1));
            mx1 = fmaxf(mx1, __shfl_xor_sync(0xffffffffu, mx1, 2));

            float mn0 = fmaxf(m_i[0], mx0), mn1 = fmaxf(m_i[1], mx1);
            float al0 = exp2f(m_i[0] - mn0), al1 = exp2f(m_i[1] - mn1);
            float ps0 = 0.0f, ps1 = 0.0f;
            const int pr0 = (wr + g) * FST;
            const int pr1 = pr0 + 8 * FST;
#pragma unroll
            for (int nt = 0; nt < 8; nt++) {
                float p0 = exp2f(s[nt][0] - mn0);
                float p1 = exp2f(s[nt][1] - mn0);
                float p2 = exp2f(s[nt][2] - mn1);
                float p3 = exp2f(s[nt][3] - mn1);
                ps0 += p0 + p1; ps1 += p2 + p3;
                int cc = nt * 8 + 2 * tg;
                *reinterpret_cast<__half2*>(&Ps[pr0 + cc]) = __floats2half2_rn(p0, p1);
                *reinterpret_cast<__half2*>(&Ps[pr1 + cc]) = __floats2half2_rn(p2, p3);
                o[nt][0] *= al0; o[nt][1] *= al0;
                o[nt][2] *= al1; o[nt][3] *= al1;
            }
            ps0 += __shfl_xor_sync(0xffffffffu, ps0, 1);
            ps0 += __shfl_xor_sync(0xffffffffu, ps0, 2);
            ps1 += __shfl_xor_sync(0xffffffffu, ps1, 1);
            ps1 += __shfl_xor_sync(0xffffffffu, ps1, 2);
            l_i[0] = l_i[0] * al0 + ps0;
            l_i[1] = l_i[1] * al1 + ps1;
            m_i[0] = mn0; m_i[1] = mn1;
        }
        __syncwarp();

        // ---- O += P V ----
#pragma unroll
        for (int kc = 0; kc < 4; kc++) {
            const uint32_t kkB = kc * 32;
            uint32_t a[4];
            ldsm_x4(a, sb + pOff + kkB);
#pragma unroll
            for (int pr = 0; pr < 4; pr++) {
                uint32_t bfr[4];
                ldsm_x4(bfr, vBase + bOff[pr] + kkB);
                mma_f16(o[pr * 2],     a, bfr);
                mma_f16(o[pr * 2 + 1], a, bfr + 2);
            }
        }
        // no trailing barrier: next iteration's top __syncthreads orders buf reuse
    }

    // ---- epilogue ----
    const float inv0 = 1.0f / l_i[0];
    const float inv1 = 1.0f / l_i[1];
    const size_t row0 = (size_t)(q0 + wr + g) * ROWQ;
    const size_t row1 = row0 + 8 * ROWQ;
#pragma unroll
    for (int nt = 0; nt < 8; nt++) {
        int cc = nt * 8 + 2 * tg;
        *reinterpret_cast<__half2*>(&Op[row0 + cc]) =
            __floats2half2_rn(o[nt][0] * inv0, o[nt][1] * inv0);
        *reinterpret_cast<__half2*>(&Op[row1 + cc]) =
            __floats2half2_rn(o[nt][2] * inv1, o[nt][3] * inv1);
    }
}

// ================= launch =====================================================
extern "C" void kernel_launch(void* const* d_in, const int* in_sizes, int n_in,
                              void* d_out, int out_size)
{
    const float* x  = (const float*)d_in[0];
    const float* Wq = (const float*)d_in[1];
    const float* Wk = (const float*)d_in[2];
    const float* Wv = (const float*)d_in[3];
    const float* Wo = (const float*)d_in[4];
    float* out = (float*)d_out;

    cudaFuncSetAttribute(flash_mma, cudaFuncAttributeMaxDynamicSharedMemorySize, FA_SMEM);
    cudaFuncSetAttribute(qkv_mma,   cudaFuncAttributeMaxDynamicSharedMemorySize, GEMM_SMEM);
    cudaFuncSetAttribute(oproj_mma, cudaFuncAttributeMaxDynamicSharedMemorySize, GEMM_SMEM);

    prep_all<<<2048 + 2560, 256>>>(x, Wq, Wk, Wv, Wo);

    qkv_mma<<<dim3(12, 32), 128, GEMM_SMEM>>>();
    transpose_v<<<dim3(64, 8), 256>>>();
    flash_mma<<<dim3(32, 16), 256, FA_SMEM>>>();
    oproj_mma<<<dim3(8, 32), 128, GEMM_SMEM>>>(out);
}

// round 12
// speedup vs baseline: 2.1585x; 1.0369x over previous
#include <cuda_runtime.h>
#include <cuda_fp16.h>
#include <cstdint>

#define S_LEN  2048
#define G_GRP  2
#define EMB    1024
#define NKV    4
#define HD     64
#define MROWS  (S_LEN * G_GRP)      // 4096
#define KVW    (NKV * HD)           // 256
#define ROWQ   (G_GRP * EMB)        // 2048 (halves)
#define ROWK   (G_GRP * KVW)        // 512  (halves)

// ---------------- scratch (all fp16) ----------------
__device__ __half g_X[MROWS * EMB];
__device__ __half g_Q[MROWS * EMB];                 // pre-scaled by SC
__device__ __half g_K[MROWS * KVW];
__device__ __half g_V[MROWS * KVW];
__device__ __half g_VT[G_GRP * NKV * HD * S_LEN];   // [(grp*4+kvh)*64+d][seq]
__device__ __half g_O[MROWS * EMB];
__device__ __half g_WT[(EMB + 2 * KVW) * EMB];
__device__ __half g_WoT[EMB * EMB];

#define SC_CONST (0.125f * 1.4426950408889634f)

// ================= helpers =================
__device__ __forceinline__ uint32_t smem_u32(const void* p) {
    uint32_t a;
    asm("{ .reg .u64 t; cvta.to.shared.u64 t, %1; cvt.u32.u64 %0, t; }" : "=r"(a) : "l"(p));
    return a;
}
__device__ __forceinline__ void mma_f16(float c[4], const uint32_t a[4], const uint32_t b[2]) {
    asm volatile(
        "mma.sync.aligned.m16n8k16.row.col.f32.f16.f16.f32 "
        "{%0,%1,%2,%3}, {%4,%5,%6,%7}, {%8,%9}, {%0,%1,%2,%3};"
        : "+f"(c[0]), "+f"(c[1]), "+f"(c[2]), "+f"(c[3])
        : "r"(a[0]), "r"(a[1]), "r"(a[2]), "r"(a[3]), "r"(b[0]), "r"(b[1]));
}
__device__ __forceinline__ void ldsm_x4(uint32_t r[4], uint32_t addr) {
    asm volatile("ldmatrix.sync.aligned.m8n8.x4.shared.b16 {%0,%1,%2,%3}, [%4];"
        : "=r"(r[0]), "=r"(r[1]), "=r"(r[2]), "=r"(r[3]) : "r"(addr));
}
__device__ __forceinline__ int ldsmA_off(int lane, int stride) {
    return ((lane & 7) + ((lane >> 3) & 1) * 8) * stride + ((lane >> 4) & 1) * 8;
}
__device__ __forceinline__ int ldsmB_off(int lane, int stride) {
    return ((lane & 7) + ((lane >> 4) & 1) * 8) * stride + ((lane >> 3) & 1) * 8;
}
__device__ __forceinline__ void cpa16(uint32_t dst, const void* src) {
    asm volatile("cp.async.cg.shared.global [%0], [%1], 16;" :: "r"(dst), "l"(src));
}
__device__ __forceinline__ void cpa_commit() { asm volatile("cp.async.commit_group;"); }
template <int N>
__device__ __forceinline__ void cpa_wait() { asm volatile("cp.async.wait_group %0;" :: "n"(N)); }
__device__ __forceinline__ uint32_t h2u(__half2 h) { return *reinterpret_cast<uint32_t*>(&h); }

// ================= fused prep: X round + all weight transposes ===============
__global__ __launch_bounds__(256) void prep_all(
    const float* __restrict__ x,
    const float* __restrict__ Wq, const float* __restrict__ Wk,
    const float* __restrict__ Wv, const float* __restrict__ Wo)
{
    __shared__ float t[32][33];
    const int b = blockIdx.x;
    if (b < 2048) {
        size_t i = (size_t)b * 256 + threadIdx.x;
        const float4* src = reinterpret_cast<const float4*>(x) + 2 * i;
        float4 v0 = src[0], v1 = src[1];
        __half2* dst = reinterpret_cast<__half2*>(g_X) + 4 * i;
        dst[0] = __floats2half2_rn(v0.x, v0.y);
        dst[1] = __floats2half2_rn(v0.z, v0.w);
        dst[2] = __floats2half2_rn(v1.x, v1.y);
        dst[3] = __floats2half2_rn(v1.z, v1.w);
        return;
    }
    const int bb = b - 2048;
    const int bx = bb % 80;
    const int by = bb / 80;
    const float* W; __half* WT; int N; int nb;
    if (bx < 32)      { W = Wq; WT = g_WT;                               N = EMB; nb = bx; }
    else if (bx < 40) { W = Wk; WT = g_WT + (size_t)EMB * EMB;           N = KVW; nb = bx - 32; }
    else if (bx < 48) { W = Wv; WT = g_WT + (size_t)(EMB + KVW) * EMB;   N = KVW; nb = bx - 40; }
    else              { W = Wo; WT = g_WoT;                              N = EMB; nb = bx - 48; }

    const int tx  = threadIdx.x & 31;
    const int ty0 = threadIdx.x >> 5;
#pragma unroll
    for (int r = 0; r < 4; r++) {
        int ty = ty0 + r * 8;
        t[ty][tx] = W[(size_t)(by * 32 + ty) * N + nb * 32 + tx];
    }
    __syncthreads();
#pragma unroll
    for (int r = 0; r < 4; r++) {
        int ty = ty0 + r * 8;
        WT[(size_t)(nb * 32 + ty) * EMB + by * 32 + tx] = __float2half(t[tx][ty]);
    }
}

// coalesced V transpose (half): g_V[m][c] -> g_VT[(m&1)*256 + c][m>>1]
__global__ __launch_bounds__(256) void transpose_v() {
    __shared__ __half t[64][33];
    const int mt = blockIdx.x;
    const int ct = blockIdx.y;
    const int tx = threadIdx.x & 31;
    const int ty = threadIdx.x >> 5;
#pragma unroll
    for (int k = 0; k < 8; k++) {
        int ml = ty + k * 8;
        t[ml][tx] = g_V[(size_t)(mt * 64 + ml) * KVW + ct * 32 + tx];
    }
    __syncthreads();
#pragma unroll
    for (int k = 0; k < 8; k++) {
        int rs  = ty + k * 8;
        int grp = rs >> 5, c = rs & 31;
        g_VT[(size_t)(grp * 256 + ct * 32 + c) * S_LEN + mt * 32 + tx] = t[grp + 2 * tx][c];
    }
}

// ================= fp16 mma GEMM: 128x128 CTA, 64x64 warp tile ==============
#define AST 72
#define ABUF_H (128 * AST)
#define GEMM_SMEM (4 * ABUF_H * 2)    // 73728 B

// OM: 0 = fp32 out, 1 = half out, 2 = half out * SC
template <int OM>
__device__ __forceinline__ void gemm_tile(
    const __half* __restrict__ A, const __half* __restrict__ BT,
    void* __restrict__ Cv, int ldc, int m0, int n0bt, int c0)
{
    extern __shared__ __half hsm[];
    const uint32_t sb = smem_u32(hsm);

    const int tid  = threadIdx.x;
    const int lane = tid & 31;
    const int wid  = tid >> 5;
    const int wm   = wid >> 1;
    const int wn   = wid & 1;
    const int g    = lane >> 2;
    const int tg   = lane & 3;

    float acc[4][8][4];
#pragma unroll
    for (int mi = 0; mi < 4; mi++)
#pragma unroll
        for (int nt = 0; nt < 8; nt++)
#pragma unroll
            for (int j = 0; j < 4; j++) acc[mi][nt][j] = 0.0f;

    const int row = tid >> 3;
    const int q   = (tid & 7) * 8;

    auto stage = [&](int c, int buf) {
        const int k0 = c * 64;
        const uint32_t aBase = sb + (uint32_t)(2 * buf) * ABUF_H * 2;
        const uint32_t bBase = aBase + ABUF_H * 2;
#pragma unroll
        for (int t = 0; t < 8; t++) {
            int r = row + t * 16;
            cpa16(aBase + (uint32_t)(r * AST + q) * 2, &A [(size_t)(m0 + r) * EMB + k0 + q]);
            cpa16(bBase + (uint32_t)(r * AST + q) * 2, &BT[(size_t)(n0bt + r) * EMB + k0 + q]);
        }
    };

    uint32_t aOff[4], bOff[4];
    {
        const int la = ldsmA_off(lane, AST);
        const int lb = ldsmB_off(lane, AST);
#pragma unroll
        for (int mi = 0; mi < 4; mi++)
            aOff[mi] = (uint32_t)(((wm * 64 + mi * 16) * AST + la) * 2);
#pragma unroll
        for (int pr = 0; pr < 4; pr++)
            bOff[pr] = (uint32_t)(((wn * 64 + pr * 16) * AST + lb) * 2);
    }

    stage(0, 0); cpa_commit();

    for (int c = 0; c < 16; c++) {
        cpa_wait<0>();                 // chunk c copies done
        __syncthreads();               // publish + gate buffer reuse
        if (c < 15) { stage(c + 1, (c + 1) & 1); cpa_commit(); }

        const uint32_t aBase = sb + (uint32_t)(2 * (c & 1)) * ABUF_H * 2;
        const uint32_t bBase = aBase + ABUF_H * 2;
#pragma unroll
        for (int kc = 0; kc < 4; kc++) {
            const uint32_t kkB = kc * 32;
            uint32_t a[4][4];
#pragma unroll
            for (int mi = 0; mi < 4; mi++)
                ldsm_x4(a[mi], aBase + aOff[mi] + kkB);
#pragma unroll
            for (int pr = 0; pr < 4; pr++) {
                uint32_t bfr[4];
                ldsm_x4(bfr, bBase + bOff[pr] + kkB);
#pragma unroll
                for (int mi = 0; mi < 4; mi++) {
                    mma_f16(acc[mi][pr * 2],     a[mi], bfr);
                    mma_f16(acc[mi][pr * 2 + 1], a[mi], bfr + 2);
                }
            }
        }
    }

#pragma unroll
    for (int mi = 0; mi < 4; mi++) {
        int r0 = m0 + wm * 64 + mi * 16 + g;
#pragma unroll
        for (int nt = 0; nt < 8; nt++) {
            int col = c0 + wn * 64 + nt * 8 + 2 * tg;
            if (OM == 0) {
                float* C = (float*)Cv;
                *reinterpret_cast<float2*>(&C[(size_t)r0 * ldc + col]) =
                    make_float2(acc[mi][nt][0], acc[mi][nt][1]);
                *reinterpret_cast<float2*>(&C[(size_t)(r0 + 8) * ldc + col]) =
                    make_float2(acc[mi][nt][2], acc[mi][nt][3]);
            } else {
                const float m = (OM == 2) ? SC_CONST : 1.0f;
                __half* C = (__half*)Cv;
                *reinterpret_cast<__half2*>(&C[(size_t)r0 * ldc + col]) =
                    __floats2half2_rn(acc[mi][nt][0] * m, acc[mi][nt][1] * m);
                *reinterpret_cast<__half2*>(&C[(size_t)(r0 + 8) * ldc + col]) =
                    __floats2half2_rn(acc[mi][nt][2] * m, acc[mi][nt][3] * m);
            }
        }
    }
}

__global__ __launch_bounds__(128, 3) void qkv_mma() {
    int nb = blockIdx.x;
    int m0 = blockIdx.y * 128;
    if (nb < 8)
        gemm_tile<2>(g_X, g_WT, g_Q, EMB, m0, nb * 128, nb * 128);
    else if (nb < 10)
        gemm_tile<1>(g_X, g_WT, g_K, KVW, m0, nb * 128, (nb - 8) * 128);
    else
        gemm_tile<1>(g_X, g_WT, g_V, KVW, m0, nb * 128, (nb - 10) * 128);
}

__global__ __launch_bounds__(128) void oproj_mma(float* __restrict__ out) {
    gemm_tile<0>(g_O, g_WoT, out, EMB, blockIdx.y * 128, blockIdx.x * 128, blockIdx.x * 128);
}

// ================= flash attention: fp16 mma, register-resident P ============
#define FST  72
#define TB_H (64 * FST)                    // halves per K/V tile
#define FA_SMEM (4 * TB_H * 2)             // 36864 B (2 K bufs + 2 V bufs)

__global__ __launch_bounds__(256, 2) void flash_mma()
{
    extern __shared__ __half fsm[];
    const uint32_t sbK0 = smem_u32(fsm);           // K buf0 | K buf1 | V buf0 | V buf1
    const uint32_t sbV0 = sbK0 + 2 * TB_H * 2;

    const int tid  = threadIdx.x;
    const int lane = tid & 31;
    const int w    = tid >> 5;
    const int g    = lane >> 2;
    const int tg   = lane & 3;
    const int wr   = w * 16;

    const int gh  = blockIdx.x;
    const int qb  = (int)gridDim.y - 1 - blockIdx.y;
    const int grp = gh & 1;
    const int h   = gh >> 1;
    const int kvh = h >> 2;

    const __half* Qp  = g_Q + grp * EMB + h * HD;
    const __half* Kp  = g_K + grp * KVW + kvh * HD;
    const __half* VTp = g_VT + (size_t)((grp * 4 + kvh) * 64) * S_LEN;
    __half*       Op  = g_O + grp * EMB + h * HD;

    const int q0 = qb * 128;

    const int laA = ldsmA_off(lane, FST);
    const int laB = ldsmB_off(lane, FST);
    const uint32_t pOff = (uint32_t)((wr * FST + laA) * 2);   // Q frag base (rel sbK0)
    uint32_t bOff[4];
#pragma unroll
    for (int pr = 0; pr < 4; pr++)
        bOff[pr] = (uint32_t)((pr * 16 * FST + laB) * 2);

    // ---- prologue: stage Q into the two K buffers (128 rows x FST), hoist ----
    {
        const int r0s = tid >> 3;
        const int qs  = (tid & 7) * 8;
#pragma unroll
        for (int p = 0; p < 4; p++) {
            int r = r0s + p * 32;
            cpa16(sbK0 + (uint32_t)(r * FST + qs) * 2, &Qp[(size_t)(q0 + r) * ROWQ + qs]);
        }
        cpa_commit();
        cpa_wait<0>();
        __syncthreads();
    }
    uint32_t aq[4][4];
#pragma unroll
    for (int kc = 0; kc < 4; kc++)
        ldsm_x4(aq[kc], sbK0 + pOff + kc * 32);
    __syncthreads();                      // K buffers now free

    // ---- K/VT staging ----
    const int srow = tid >> 3;
    const int sq   = (tid & 7) * 8;
    auto stage_kv = [&](int kb, int buf) {
        const int kn = kb * 64;
        const uint32_t kBase = sbK0 + (uint32_t)buf * TB_H * 2;
        const uint32_t vBase = sbV0 + (uint32_t)buf * TB_H * 2;
#pragma unroll
        for (int p = 0; p < 2; p++) {
            int r = srow + p * 32;
            cpa16(kBase + (uint32_t)(r * FST + sq) * 2, &Kp[(size_t)(kn + r) * ROWK + sq]);
            cpa16(vBase + (uint32_t)(r * FST + sq) * 2, &VTp[(size_t)r * S_LEN + kn + sq]);
        }
    };

    float m_i[2] = {-1e30f, -1e30f};
    float l_i[2] = {0.0f, 0.0f};
    float o[8][4];
#pragma unroll
    for (int nt = 0; nt < 8; nt++)
#pragma unroll
        for (int j = 0; j < 4; j++) o[nt][j] = 0.0f;

    const int kbmax = 2 * qb + 1;
    stage_kv(0, 0);
    cpa_commit();

    for (int kb = 0; kb <= kbmax; kb++) {
        const int kn  = kb * 64;
        const int buf = kb & 1;

        cpa_wait<0>();
        __syncthreads();
        if (kb < kbmax) { stage_kv(kb + 1, buf ^ 1); cpa_commit(); }

        const uint32_t kBase = sbK0 + (uint32_t)buf * TB_H * 2;
        const uint32_t vBase = sbV0 + (uint32_t)buf * TB_H * 2;

        // ---- S = (Q*SC) K^T ----
        float s[8][4];
#pragma unroll
        for (int nt = 0; nt < 8; nt++)
#pragma unroll
            for (int j = 0; j < 4; j++) s[nt][j] = 0.0f;

#pragma unroll
        for (int kc = 0; kc < 4; kc++) {
            const uint32_t kkB = kc * 32;
#pragma unroll
            for (int pr = 0; pr < 4; pr++) {
                uint32_t bfr[4];
                ldsm_x4(bfr, kBase + bOff[pr] + kkB);
                mma_f16(s[pr * 2],     aq[kc], bfr);
                mma_f16(s[pr * 2 + 1], aq[kc], bfr + 2);
            }
        }

        // ---- online softmax (base-2), P packed directly into PV A-fragments ---
        uint32_t pa[4][4];
        const bool diag = (kn + 63 > q0);
        {
            const int r0 = q0 + wr + g;
            const int r1 = r0 + 8;
            float mx0 = -1e30f, mx1 = -1e30f;
#pragma unroll
            for (int nt = 0; nt < 8; nt++) {
                int cc = kn + nt * 8 + 2 * tg;
                float v0 = s[nt][0], v1 = s[nt][1], v2 = s[nt][2], v3 = s[nt][3];
                if (diag) {
                    if (cc > r0)     v0 = -1e30f;
                    if (cc + 1 > r0) v1 = -1e30f;
                    if (cc > r1)     v2 = -1e30f;
                    if (cc + 1 > r1) v3 = -1e30f;
                }
                s[nt][0] = v0; s[nt][1] = v1; s[nt][2] = v2; s[nt][3] = v3;
                mx0 = fmaxf(mx0, fmaxf(v0, v1));
                mx1 = fmaxf(mx1, fmaxf(v2, v3));
            }
            mx0 = fmaxf(mx0, __shfl_xor_sync(0xffffffffu, mx0, 1));
            mx0 = fmaxf(mx0, __shfl_xor_sync(0xffffffffu, mx0, 2));
            mx1 = fmaxf(mx1, __shfl_xor_sync(0xffffffffu, mx1, 1));
            mx1 = fmaxf(mx1, __shfl_xor_sync(0xffffffffu, mx1, 2));

            float mn0 = fmaxf(m_i[0], mx0), mn1 = fmaxf(m_i[1], mx1);
            float al0 = exp2f(m_i[0] - mn0), al1 = exp2f(m_i[1] - mn1);
            float ps0 = 0.0f, ps1 = 0.0f;
#pragma unroll
            for (int nt = 0; nt < 8; nt++) {
                float p0 = exp2f(s[nt][0] - mn0);
                float p1 = exp2f(s[nt][1] - mn0);
                float p2 = exp2f(s[nt][2] - mn1);
                float p3 = exp2f(s[nt][3] - mn1);
                ps0 += p0 + p1; ps1 += p2 + p3;
                // A-fragment identity: kc = nt>>1; even nt -> regs 0,1; odd -> 2,3
                const int kc = nt >> 1;
                if ((nt & 1) == 0) {
                    pa[kc][0] = h2u(__floats2half2_rn(p0, p1));
                    pa[kc][1] = h2u(__floats2half2_rn(p2, p3));
                } else {
                    pa[kc][2] = h2u(__floats2half2_rn(p0, p1));
                    pa[kc][3] = h2u(__floats2half2_rn(p2, p3));
                }
                o[nt][0] *= al0; o[nt][1] *= al0;
                o[nt][2] *= al1; o[nt][3] *= al1;
            }
            ps0 += __shfl_xor_sync(0xffffffffu, ps0, 1);
            ps0 += __shfl_xor_sync(0xffffffffu, ps0, 2);
            ps1 += __shfl_xor_sync(0xffffffffu, ps1, 1);
            ps1 += __shfl_xor_sync(0xffffffffu, ps1, 2);
            l_i[0] = l_i[0] * al0 + ps0;
            l_i[1] = l_i[1] * al1 + ps1;
            m_i[0] = mn0; m_i[1] = mn1;
        }

        // ---- O += P V (P from registers, V via LDSM) ----
#pragma unroll
        for (int kc = 0; kc < 4; kc++) {
            const uint32_t kkB = kc * 32;
#pragma unroll
            for (int pr = 0; pr < 4; pr++) {
                uint32_t bfr[4];
                ldsm_x4(bfr, vBase + bOff[pr] + kkB);
                mma_f16(o[pr * 2],     pa[kc], bfr);
                mma_f16(o[pr * 2 + 1], pa[kc], bfr + 2);
            }
        }
    }

    // ---- epilogue ----
    const float inv0 = 1.0f / l_i[0];
    const float inv1 = 1.0f / l_i[1];
    const size_t row0 = (size_t)(q0 + wr + g) * ROWQ;
    const size_t row1 = row0 + 8 * ROWQ;
#pragma unroll
    for (int nt = 0; nt < 8; nt++) {
        int cc = nt * 8 + 2 * tg;
        *reinterpret_cast<__half2*>(&Op[row0 + cc]) =
            __floats2half2_rn(o[nt][0] * inv0, o[nt][1] * inv0);
        *reinterpret_cast<__half2*>(&Op[row1 + cc]) =
            __floats2half2_rn(o[nt][2] * inv1, o[nt][3] * inv1);
    }
}

// ================= launch =====================================================
extern "C" void kernel_launch(void* const* d_in, const int* in_sizes, int n_in,
                              void* d_out, int out_size)
{
    const float* x  = (const float*)d_in[0];
    const float* Wq = (const float*)d_in[1];
    const float* Wk = (const float*)d_in[2];
    const float* Wv = (const float*)d_in[3];
    const float* Wo = (const float*)d_in[4];
    float* out = (float*)d_out;

    cudaFuncSetAttribute(flash_mma, cudaFuncAttributeMaxDynamicSharedMemorySize, FA_SMEM);
    cudaFuncSetAttribute(qkv_mma,   cudaFuncAttributeMaxDynamicSharedMemorySize, GEMM_SMEM);
    cudaFuncSetAttribute(oproj_mma, cudaFuncAttributeMaxDynamicSharedMemorySize, GEMM_SMEM);

    prep_all<<<2048 + 2560, 256>>>(x, Wq, Wk, Wv, Wo);

    qkv_mma<<<dim3(12, 32), 128, GEMM_SMEM>>>();
    transpose_v<<<dim3(64, 8), 256>>>();
    flash_mma<<<dim3(32, 16), 256, FA_SMEM>>>();
    oproj_mma<<<dim3(8, 32), 128, GEMM_SMEM>>>(out);
}

// round 13
// speedup vs baseline: 2.3016x; 1.0663x over previous
#include <cuda_runtime.h>
#include <cuda_fp16.h>
#include <cstdint>

#define S_LEN  2048
#define G_GRP  2
#define EMB    1024
#define NKV    4
#define HD     64
#define MROWS  (S_LEN * G_GRP)      // 4096
#define KVW    (NKV * HD)           // 256
#define ROWQ   (G_GRP * EMB)        // 2048 (halves)
#define ROWK   (G_GRP * KVW)        // 512  (halves)

// ---------------- scratch (all fp16) ----------------
__device__ __half g_X[MROWS * EMB];
__device__ __half g_Q[MROWS * EMB];                 // pre-scaled by SC
__device__ __half g_K[MROWS * KVW];
__device__ __half g_V[MROWS * KVW];
__device__ __half g_VT[G_GRP * NKV * HD * S_LEN];   // [(grp*4+kvh)*64+d][seq]
__device__ __half g_O[MROWS * EMB];
__device__ __half g_WT[(EMB + 2 * KVW) * EMB];
__device__ __half g_WoT[EMB * EMB];

#define SC_CONST (0.125f * 1.4426950408889634f)

// ================= helpers =================
__device__ __forceinline__ uint32_t smem_u32(const void* p) {
    uint32_t a;
    asm("{ .reg .u64 t; cvta.to.shared.u64 t, %1; cvt.u32.u64 %0, t; }" : "=r"(a) : "l"(p));
    return a;
}
__device__ __forceinline__ void mma_f16(float c[4], const uint32_t a[4], const uint32_t b[2]) {
    asm volatile(
        "mma.sync.aligned.m16n8k16.row.col.f32.f16.f16.f32 "
        "{%0,%1,%2,%3}, {%4,%5,%6,%7}, {%8,%9}, {%0,%1,%2,%3};"
        : "+f"(c[0]), "+f"(c[1]), "+f"(c[2]), "+f"(c[3])
        : "r"(a[0]), "r"(a[1]), "r"(a[2]), "r"(a[3]), "r"(b[0]), "r"(b[1]));
}
__device__ __forceinline__ void ldsm_x4(uint32_t r[4], uint32_t addr) {
    asm volatile("ldmatrix.sync.aligned.m8n8.x4.shared.b16 {%0,%1,%2,%3}, [%4];"
        : "=r"(r[0]), "=r"(r[1]), "=r"(r[2]), "=r"(r[3]) : "r"(addr));
}
__device__ __forceinline__ int ldsmA_off(int lane, int stride) {
    return ((lane & 7) + ((lane >> 3) & 1) * 8) * stride + ((lane >> 4) & 1) * 8;
}
__device__ __forceinline__ int ldsmB_off(int lane, int stride) {
    return ((lane & 7) + ((lane >> 4) & 1) * 8) * stride + ((lane >> 3) & 1) * 8;
}
__device__ __forceinline__ void cpa16(uint32_t dst, const void* src) {
    asm volatile("cp.async.cg.shared.global [%0], [%1], 16;" :: "r"(dst), "l"(src));
}
__device__ __forceinline__ void cpa_commit() { asm volatile("cp.async.commit_group;"); }
template <int N>
__device__ __forceinline__ void cpa_wait() { asm volatile("cp.async.wait_group %0;" :: "n"(N)); }
__device__ __forceinline__ uint32_t h2u(__half2 h) { return *reinterpret_cast<uint32_t*>(&h); }
__device__ __forceinline__ uint32_t h2exp2(uint32_t x) {
    uint32_t r;
    asm("ex2.approx.f16x2 %0, %1;" : "=r"(r) : "r"(x));
    return r;
}

// ================= fused prep: X round + all weight transposes ===============
__global__ __launch_bounds__(256) void prep_all(
    const float* __restrict__ x,
    const float* __restrict__ Wq, const float* __restrict__ Wk,
    const float* __restrict__ Wv, const float* __restrict__ Wo)
{
    __shared__ float t[32][33];
    const int b = blockIdx.x;
    if (b < 2048) {
        size_t i = (size_t)b * 256 + threadIdx.x;
        const float4* src = reinterpret_cast<const float4*>(x) + 2 * i;
        float4 v0 = src[0], v1 = src[1];
        __half2* dst = reinterpret_cast<__half2*>(g_X) + 4 * i;
        dst[0] = __floats2half2_rn(v0.x, v0.y);
        dst[1] = __floats2half2_rn(v0.z, v0.w);
        dst[2] = __floats2half2_rn(v1.x, v1.y);
        dst[3] = __floats2half2_rn(v1.z, v1.w);
        return;
    }
    const int bb = b - 2048;
    const int bx = bb % 80;
    const int by = bb / 80;
    const float* W; __half* WT; int N; int nb;
    if (bx < 32)      { W = Wq; WT = g_WT;                               N = EMB; nb = bx; }
    else if (bx < 40) { W = Wk; WT = g_WT + (size_t)EMB * EMB;           N = KVW; nb = bx - 32; }
    else if (bx < 48) { W = Wv; WT = g_WT + (size_t)(EMB + KVW) * EMB;   N = KVW; nb = bx - 40; }
    else              { W = Wo; WT = g_WoT;                              N = EMB; nb = bx - 48; }

    const int tx  = threadIdx.x & 31;
    const int ty0 = threadIdx.x >> 5;
#pragma unroll
    for (int r = 0; r < 4; r++) {
        int ty = ty0 + r * 8;
        t[ty][tx] = W[(size_t)(by * 32 + ty) * N + nb * 32 + tx];
    }
    __syncthreads();
#pragma unroll
    for (int r = 0; r < 4; r++) {
        int ty = ty0 + r * 8;
        WT[(size_t)(nb * 32 + ty) * EMB + by * 32 + tx] = __float2half(t[tx][ty]);
    }
}

// coalesced V transpose (half): g_V[m][c] -> g_VT[(m&1)*256 + c][m>>1]
__global__ __launch_bounds__(256) void transpose_v() {
    __shared__ __half t[64][33];
    const int mt = blockIdx.x;
    const int ct = blockIdx.y;
    const int tx = threadIdx.x & 31;
    const int ty = threadIdx.x >> 5;
#pragma unroll
    for (int k = 0; k < 8; k++) {
        int ml = ty + k * 8;
        t[ml][tx] = g_V[(size_t)(mt * 64 + ml) * KVW + ct * 32 + tx];
    }
    __syncthreads();
#pragma unroll
    for (int k = 0; k < 8; k++) {
        int rs  = ty + k * 8;
        int grp = rs >> 5, c = rs & 31;
        g_VT[(size_t)(grp * 256 + ct * 32 + c) * S_LEN + mt * 32 + tx] = t[grp + 2 * tx][c];
    }
}

// ================= fp16 mma GEMM: 128x128 CTA, 64x64 warp tile ==============
#define AST 72
#define ABUF_H (128 * AST)
#define GEMM_SMEM (4 * ABUF_H * 2)    // 73728 B

// OM: 0 = fp32 out, 1 = half out, 2 = half out * SC
template <int OM>
__device__ __forceinline__ void gemm_tile(
    const __half* __restrict__ A, const __half* __restrict__ BT,
    void* __restrict__ Cv, int ldc, int m0, int n0bt, int c0)
{
    extern __shared__ __half hsm[];
    const uint32_t sb = smem_u32(hsm);

    const int tid  = threadIdx.x;
    const int lane = tid & 31;
    const int wid  = tid >> 5;
    const int wm   = wid >> 1;
    const int wn   = wid & 1;
    const int g    = lane >> 2;
    const int tg   = lane & 3;

    float acc[4][8][4];
#pragma unroll
    for (int mi = 0; mi < 4; mi++)
#pragma unroll
        for (int nt = 0; nt < 8; nt++)
#pragma unroll
            for (int j = 0; j < 4; j++) acc[mi][nt][j] = 0.0f;

    const int row = tid >> 3;
    const int q   = (tid & 7) * 8;

    auto stage = [&](int c, int buf) {
        const int k0 = c * 64;
        const uint32_t aBase = sb + (uint32_t)(2 * buf) * ABUF_H * 2;
        const uint32_t bBase = aBase + ABUF_H * 2;
#pragma unroll
        for (int t = 0; t < 8; t++) {
            int r = row + t * 16;
            cpa16(aBase + (uint32_t)(r * AST + q) * 2, &A [(size_t)(m0 + r) * EMB + k0 + q]);
            cpa16(bBase + (uint32_t)(r * AST + q) * 2, &BT[(size_t)(n0bt + r) * EMB + k0 + q]);
        }
    };

    uint32_t aOff[4], bOff[4];
    {
        const int la = ldsmA_off(lane, AST);
        const int lb = ldsmB_off(lane, AST);
#pragma unroll
        for (int mi = 0; mi < 4; mi++)
            aOff[mi] = (uint32_t)(((wm * 64 + mi * 16) * AST + la) * 2);
#pragma unroll
        for (int pr = 0; pr < 4; pr++)
            bOff[pr] = (uint32_t)(((wn * 64 + pr * 16) * AST + lb) * 2);
    }

    stage(0, 0); cpa_commit();

    for (int c = 0; c < 16; c++) {
        cpa_wait<0>();
        __syncthreads();
        if (c < 15) { stage(c + 1, (c + 1) & 1); cpa_commit(); }

        const uint32_t aBase = sb + (uint32_t)(2 * (c & 1)) * ABUF_H * 2;
        const uint32_t bBase = aBase + ABUF_H * 2;
#pragma unroll
        for (int kc = 0; kc < 4; kc++) {
            const uint32_t kkB = kc * 32;
            uint32_t a[4][4];
#pragma unroll
            for (int mi = 0; mi < 4; mi++)
                ldsm_x4(a[mi], aBase + aOff[mi] + kkB);
#pragma unroll
            for (int pr = 0; pr < 4; pr++) {
                uint32_t bfr[4];
                ldsm_x4(bfr, bBase + bOff[pr] + kkB);
#pragma unroll
                for (int mi = 0; mi < 4; mi++) {
                    mma_f16(acc[mi][pr * 2],     a[mi], bfr);
                    mma_f16(acc[mi][pr * 2 + 1], a[mi], bfr + 2);
                }
            }
        }
    }

#pragma unroll
    for (int mi = 0; mi < 4; mi++) {
        int r0 = m0 + wm * 64 + mi * 16 + g;
#pragma unroll
        for (int nt = 0; nt < 8; nt++) {
            int col = c0 + wn * 64 + nt * 8 + 2 * tg;
            if (OM == 0) {
                float* C = (float*)Cv;
                *reinterpret_cast<float2*>(&C[(size_t)r0 * ldc + col]) =
                    make_float2(acc[mi][nt][0], acc[mi][nt][1]);
                *reinterpret_cast<float2*>(&C[(size_t)(r0 + 8) * ldc + col]) =
                    make_float2(acc[mi][nt][2], acc[mi][nt][3]);
            } else {
                const float m = (OM == 2) ? SC_CONST : 1.0f;
                __half* C = (__half*)Cv;
                *reinterpret_cast<__half2*>(&C[(size_t)r0 * ldc + col]) =
                    __floats2half2_rn(acc[mi][nt][0] * m, acc[mi][nt][1] * m);
                *reinterpret_cast<__half2*>(&C[(size_t)(r0 + 8) * ldc + col]) =
                    __floats2half2_rn(acc[mi][nt][2] * m, acc[mi][nt][3] * m);
            }
        }
    }
}

__global__ __launch_bounds__(128, 3) void qkv_mma() {
    int nb = blockIdx.x;
    int m0 = blockIdx.y * 128;
    if (nb < 8)
        gemm_tile<2>(g_X, g_WT, g_Q, EMB, m0, nb * 128, nb * 128);
    else if (nb < 10)
        gemm_tile<1>(g_X, g_WT, g_K, KVW, m0, nb * 128, (nb - 8) * 128);
    else
        gemm_tile<1>(g_X, g_WT, g_V, KVW, m0, nb * 128, (nb - 10) * 128);
}

__global__ __launch_bounds__(128, 3) void oproj_mma(float* __restrict__ out) {
    gemm_tile<0>(g_O, g_WoT, out, EMB, blockIdx.y * 128, blockIdx.x * 128, blockIdx.x * 128);
}

// ================= flash attention: fp16 mma, register P, f16x2 exp ==========
#define FST  72
#define TB_H (64 * FST)
#define FA_SMEM (4 * TB_H * 2)             // 36864 B

__global__ __launch_bounds__(256, 2) void flash_mma()
{
    extern __shared__ __half fsm[];
    const uint32_t sbK0 = smem_u32(fsm);
    const uint32_t sbV0 = sbK0 + 2 * TB_H * 2;

    const int tid  = threadIdx.x;
    const int lane = tid & 31;
    const int w    = tid >> 5;
    const int g    = lane >> 2;
    const int tg   = lane & 3;
    const int wr   = w * 16;

    const int gh  = blockIdx.x;
    const int qb  = (int)gridDim.y - 1 - blockIdx.y;
    const int grp = gh & 1;
    const int h   = gh >> 1;
    const int kvh = h >> 2;

    const __half* Qp  = g_Q + grp * EMB + h * HD;
    const __half* Kp  = g_K + grp * KVW + kvh * HD;
    const __half* VTp = g_VT + (size_t)((grp * 4 + kvh) * 64) * S_LEN;
    __half*       Op  = g_O + grp * EMB + h * HD;

    const int q0 = qb * 128;

    const int laA = ldsmA_off(lane, FST);
    const int laB = ldsmB_off(lane, FST);
    const uint32_t pOff = (uint32_t)((wr * FST + laA) * 2);
    uint32_t bOff[4];
#pragma unroll
    for (int pr = 0; pr < 4; pr++)
        bOff[pr] = (uint32_t)((pr * 16 * FST + laB) * 2);

    // ---- prologue: stage Q into the two K buffers, hoist fragments ----
    {
        const int r0s = tid >> 3;
        const int qs  = (tid & 7) * 8;
#pragma unroll
        for (int p = 0; p < 4; p++) {
            int r = r0s + p * 32;
            cpa16(sbK0 + (uint32_t)(r * FST + qs) * 2, &Qp[(size_t)(q0 + r) * ROWQ + qs]);
        }
        cpa_commit();
        cpa_wait<0>();
        __syncthreads();
    }
    uint32_t aq[4][4];
#pragma unroll
    for (int kc = 0; kc < 4; kc++)
        ldsm_x4(aq[kc], sbK0 + pOff + kc * 32);
    __syncthreads();

    // ---- K/VT staging ----
    const int srow = tid >> 3;
    const int sq   = (tid & 7) * 8;
    auto stage_kv = [&](int kb, int buf) {
        const int kn = kb * 64;
        const uint32_t kBase = sbK0 + (uint32_t)buf * TB_H * 2;
        const uint32_t vBase = sbV0 + (uint32_t)buf * TB_H * 2;
#pragma unroll
        for (int p = 0; p < 2; p++) {
            int r = srow + p * 32;
            cpa16(kBase + (uint32_t)(r * FST + sq) * 2, &Kp[(size_t)(kn + r) * ROWK + sq]);
            cpa16(vBase + (uint32_t)(r * FST + sq) * 2, &VTp[(size_t)r * S_LEN + kn + sq]);
        }
    };

    float m_i[2] = {-1e30f, -1e30f};
    float l_i[2] = {0.0f, 0.0f};
    float o[8][4];
#pragma unroll
    for (int nt = 0; nt < 8; nt++)
#pragma unroll
        for (int j = 0; j < 4; j++) o[nt][j] = 0.0f;

    const int kbmax = 2 * qb + 1;
    stage_kv(0, 0);
    cpa_commit();

    for (int kb = 0; kb <= kbmax; kb++) {
        const int kn  = kb * 64;
        const int buf = kb & 1;

        cpa_wait<0>();
        __syncthreads();
        if (kb < kbmax) { stage_kv(kb + 1, buf ^ 1); cpa_commit(); }

        const uint32_t kBase = sbK0 + (uint32_t)buf * TB_H * 2;
        const uint32_t vBase = sbV0 + (uint32_t)buf * TB_H * 2;

        // ---- S = (Q*SC) K^T ----
        float s[8][4];
#pragma unroll
        for (int nt = 0; nt < 8; nt++)
#pragma unroll
            for (int j = 0; j < 4; j++) s[nt][j] = 0.0f;

#pragma unroll
        for (int kc = 0; kc < 4; kc++) {
            const uint32_t kkB = kc * 32;
#pragma unroll
            for (int pr = 0; pr < 4; pr++) {
                uint32_t bfr[4];
                ldsm_x4(bfr, kBase + bOff[pr] + kkB);
                mma_f16(s[pr * 2],     aq[kc], bfr);
                mma_f16(s[pr * 2 + 1], aq[kc], bfr + 2);
            }
        }

        // ---- online softmax: fp32 subtract, f16x2 exp2, P -> A-fragments -----
        uint32_t pa[4][4];
        const bool diag = (kn + 63 > q0);
        {
            const int r0 = q0 + wr + g;
            const int r1 = r0 + 8;
            float mx0 = -1e30f, mx1 = -1e30f;
#pragma unroll
            for (int nt = 0; nt < 8; nt++) {
                int cc = kn + nt * 8 + 2 * tg;
                float v0 = s[nt][0], v1 = s[nt][1], v2 = s[nt][2], v3 = s[nt][3];
                if (diag) {
                    if (cc > r0)     v0 = -1e30f;
                    if (cc + 1 > r0) v1 = -1e30f;
                    if (cc > r1)     v2 = -1e30f;
                    if (cc + 1 > r1) v3 = -1e30f;
                }
                s[nt][0] = v0; s[nt][1] = v1; s[nt][2] = v2; s[nt][3] = v3;
                mx0 = fmaxf(mx0, fmaxf(v0, v1));
                mx1 = fmaxf(mx1, fmaxf(v2, v3));
            }
            mx0 = fmaxf(mx0, __shfl_xor_sync(0xffffffffu, mx0, 1));
            mx0 = fmaxf(mx0, __shfl_xor_sync(0xffffffffu, mx0, 2));
            mx1 = fmaxf(mx1, __shfl_xor_sync(0xffffffffu, mx1, 1));
            mx1 = fmaxf(mx1, __shfl_xor_sync(0xffffffffu, mx1, 2));

            float mn0 = fmaxf(m_i[0], mx0), mn1 = fmaxf(m_i[1], mx1);
            float al0 = exp2f(m_i[0] - mn0), al1 = exp2f(m_i[1] - mn1);
            float ps0 = 0.0f, ps1 = 0.0f;
#pragma unroll
            for (int nt = 0; nt < 8; nt++) {
                // exponent-domain differences in fp32, exp in f16x2
                uint32_t d01 = h2u(__floats2half2_rn(s[nt][0] - mn0, s[nt][1] - mn0));
                uint32_t d23 = h2u(__floats2half2_rn(s[nt][2] - mn1, s[nt][3] - mn1));
                uint32_t p01 = h2exp2(d01);
                uint32_t p23 = h2exp2(d23);
                const int kc = nt >> 1;
                if ((nt & 1) == 0) {
                    pa[kc][0] = p01;
                    pa[kc][1] = p23;
                } else {
                    pa[kc][2] = p01;
                    pa[kc][3] = p23;
                }
                float2 f01 = __half22float2(*reinterpret_cast<__half2*>(&p01));
                float2 f23 = __half22float2(*reinterpret_cast<__half2*>(&p23));
                ps0 += f01.x + f01.y;
                ps1 += f23.x + f23.y;
                o[nt][0] *= al0; o[nt][1] *= al0;
                o[nt][2] *= al1; o[nt][3] *= al1;
            }
            ps0 += __shfl_xor_sync(0xffffffffu, ps0, 1);
            ps0 += __shfl_xor_sync(0xffffffffu, ps0, 2);
            ps1 += __shfl_xor_sync(0xffffffffu, ps1, 1);
            ps1 += __shfl_xor_sync(0xffffffffu, ps1, 2);
            l_i[0] = l_i[0] * al0 + ps0;
            l_i[1] = l_i[1] * al1 + ps1;
            m_i[0] = mn0; m_i[1] = mn1;
        }

        // ---- O += P V (P from registers, V via LDSM) ----
#pragma unroll
        for (int kc = 0; kc < 4; kc++) {
            const uint32_t kkB = kc * 32;
#pragma unroll
            for (int pr = 0; pr < 4; pr++) {
                uint32_t bfr[4];
                ldsm_x4(bfr, vBase + bOff[pr] + kkB);
                mma_f16(o[pr * 2],     pa[kc], bfr);
                mma_f16(o[pr * 2 + 1], pa[kc], bfr + 2);
            }
        }
    }

    // ---- epilogue ----
    const float inv0 = 1.0f / l_i[0];
    const float inv1 = 1.0f / l_i[1];
    const size_t row0 = (size_t)(q0 + wr + g) * ROWQ;
    const size_t row1 = row0 + 8 * ROWQ;
#pragma unroll
    for (int nt = 0; nt < 8; nt++) {
        int cc = nt * 8 + 2 * tg;
        *reinterpret_cast<__half2*>(&Op[row0 + cc]) =
            __floats2half2_rn(o[nt][0] * inv0, o[nt][1] * inv0);
        *reinterpret_cast<__half2*>(&Op[row1 + cc]) =
            __floats2half2_rn(o[nt][2] * inv1, o[nt][3] * inv1);
    }
}

// ================= launch =====================================================
extern "C" void kernel_launch(void* const* d_in, const int* in_sizes, int n_in,
                              void* d_out, int out_size)
{
    const float* x  = (const float*)d_in[0];
    const float* Wq = (const float*)d_in[1];
    const float* Wk = (const float*)d_in[2];
    const float* Wv = (const float*)d_in[3];
    const float* Wo = (const float*)d_in[4];
    float* out = (float*)d_out;

    cudaFuncSetAttribute(flash_mma, cudaFuncAttributeMaxDynamicSharedMemorySize, FA_SMEM);
    cudaFuncSetAttribute(qkv_mma,   cudaFuncAttributeMaxDynamicSharedMemorySize, GEMM_SMEM);
    cudaFuncSetAttribute(oproj_mma, cudaFuncAttributeMaxDynamicSharedMemorySize, GEMM_SMEM);

    prep_all<<<2048 + 2560, 256>>>(x, Wq, Wk, Wv, Wo);

    qkv_mma<<<dim3(12, 32), 128, GEMM_SMEM>>>();
    transpose_v<<<dim3(64, 8), 256>>>();
    flash_mma<<<dim3(32, 16), 256, FA_SMEM>>>();
    oproj_mma<<<dim3(8, 32), 128, GEMM_SMEM>>>(out);
}